// round 15
// baseline (speedup 1.0000x reference)
#include <cuda_runtime.h>
#include <cuda_fp16.h>
#include <math.h>
#include <stdint.h>

// Problem constants
#define BB   4
#define LQd  256
#define NSd  24
#define NTd  128
#define Dd   512
#define Hd   8
#define DKd  64

// ---------------- scratch layout ----------------
#define OFF_QS   0
#define OFF_KS   524288
#define OFF_VS   573440
#define OFF_ATT  622592
#define OFF_HALF 819200
#define H_ACTH 0
#define H_ACTL 13205504
#define H_WTH  26411008
#define H_WTL  29032448
#define H_QWH  31653888
#define H_QWL  32178176
#define H_KWH  32702464
#define H_KWL  38993920
#define H_VWH  45285376
#define H_VWL  51576832
#define H_CSH  57868288
#define H_CSL  58392576
#define H_CWH  58916864
#define H_CWL  59441152
#define H_CATH 59965440
#define H_CATL 61014016
#define H_TOTAL 62062592
#define SCRATCH_TOTAL (OFF_HALF + H_TOTAL / 2)
__device__ float g_scratch[SCRATCH_TOTAL];

#define AQ   0
#define AKS  524288
#define AVS  573440
#define AKW  622592
#define AVW  6914048
#define WOFF(i) ((i) * 262144)

// ---------------- helpers ----------------
__device__ __forceinline__ void split_h(float x, __half& hi, __half& lo) {
    hi = __float2half_rn(x);
    lo = __float2half_rn(x - __half2float(hi));
}
__device__ __forceinline__ void mma_f16(float d[4],
                                        uint32_t a0, uint32_t a1, uint32_t a2, uint32_t a3,
                                        uint32_t b0, uint32_t b1) {
    asm volatile(
        "mma.sync.aligned.m16n8k16.row.col.f32.f16.f16.f32 "
        "{%0,%1,%2,%3},{%4,%5,%6,%7},{%8,%9},{%0,%1,%2,%3};"
        : "+f"(d[0]), "+f"(d[1]), "+f"(d[2]), "+f"(d[3])
        : "r"(a0), "r"(a1), "r"(a2), "r"(a3), "r"(b0), "r"(b1));
}
__device__ __forceinline__ void ldsm_x4(uint32_t r[4], uint32_t addr) {
    asm volatile("ldmatrix.sync.aligned.m8n8.x4.shared.b16 {%0,%1,%2,%3}, [%4];"
                 : "=r"(r[0]), "=r"(r[1]), "=r"(r[2]), "=r"(r[3]) : "r"(addr));
}
__device__ __forceinline__ void ldsm_x4_t(uint32_t r[4], uint32_t addr) {
    asm volatile("ldmatrix.sync.aligned.m8n8.x4.trans.shared.b16 {%0,%1,%2,%3}, [%4];"
                 : "=r"(r[0]), "=r"(r[1]), "=r"(r[2]), "=r"(r[3]) : "r"(addr));
}
__device__ __forceinline__ void cp_async16(uint32_t smem_addr, const void* gptr, int src_bytes) {
    asm volatile("cp.async.cg.shared.global [%0], [%1], 16, %2;"
                 :: "r"(smem_addr), "l"(gptr), "r"(src_bytes) : "memory");
}
__device__ __forceinline__ void cp_commit() { asm volatile("cp.async.commit_group;" ::: "memory"); }
template <int N>
__device__ __forceinline__ void cp_wait() { asm volatile("cp.async.wait_group %0;" :: "n"(N) : "memory"); }

// ---------------- prep: convert activations to fp16 ----------------
struct ASplitArgs { const float* src[5]; };
__constant__ int c_alen[5] = {524288, 49152, 49152, 6291456, 6291456};
__constant__ int c_aoff[5] = {AQ, AKS, AVS, AKW, AVW};

__global__ __launch_bounds__(256) void act_split(ASplitArgs args, __half* acth)
{
    int z = blockIdx.y;
    int n = c_alen[z];
    const float* s = args.src[z];
    __half* dh = acth + c_aoff[z];
    for (int i = blockIdx.x * 256 + threadIdx.x; i < n; i += gridDim.x * 256) {
        dh[i] = __float2half_rn(s[i]);
    }
}

// ---------------- prep: transpose+split weights ----------------
struct WSplitArgs { const float* src[9]; };
__constant__ int c_wK[9] = {512, 512, 512, 512, 512, 512, 512, 512, 1024};
__constant__ int c_woff[9] = {WOFF(0), WOFF(1), WOFF(2), WOFF(3), WOFF(4),
                              WOFF(5), WOFF(6), WOFF(7), WOFF(8)};
__constant__ float c_wscale[9] = {1.f, 1.f, 1.f, 0.125f, 1.f, 1.f, 1.f, 1.f, 1.f};

__global__ void w_transplit(WSplitArgs args, __half* wth, __half* wtl)
{
    int z = blockIdx.z;
    int Kw = c_wK[z];
    int k0 = blockIdx.y * 32;
    if (k0 >= Kw) return;
    int n0 = blockIdx.x * 32;
    const float* W = args.src[z];
    float sc = c_wscale[z];
    __half* th = wth + c_woff[z];
    __half* tl = wtl + c_woff[z];

    __shared__ float ts[32][33];
    int tx = threadIdx.x, ty = threadIdx.y;
    #pragma unroll
    for (int r = 0; r < 4; r++)
        ts[ty + 8 * r][tx] = W[(size_t)(k0 + ty + 8 * r) * 512 + n0 + tx];
    __syncthreads();
    #pragma unroll
    for (int r = 0; r < 4; r++) {
        int n = n0 + ty + 8 * r;
        int k = k0 + tx;
        __half hi, lo;
        split_h(sc * ts[tx][ty + 8 * r], hi, lo);
        th[(size_t)n * Kw + k] = hi;
        tl[(size_t)n * Kw + k] = lo;
    }
}

// ---------------- 2-term GEMM: A fp16, B split hi/lo, 3-stage pipeline ----------------
// mode: 0 = fp32 out, 1 = split fp16 hi+lo out, 2 = fp16 hi only
#define HAS 40
#define G_A 128
#define G_B 64
#define HSTAGE ((G_A + 2 * G_B) * HAS)
#define HSMEM_BYTES (3 * HSTAGE * 2)

struct GemmCfg {
    const __half* Ah[6];
    const __half* Bh[6]; const __half* Bl[6];
    const float* bias[6];
    float* Cf[6];
    __half* Ch[6]; __half* Cl[6];
    int M[6]; int mode[6]; float bscale[6];
    int K; int ldc;
};

__global__ __launch_bounds__(256, 2) void gemm_cfg(GemmCfg cfg)
{
    extern __shared__ __half hsm[];

    const int z = blockIdx.z;
    const int M = cfg.M[z];
    const int row0 = blockIdx.y * 128;
    if (row0 >= M) return;

    const __half* Ah_g = cfg.Ah[z];
    const __half* Bh_g = cfg.Bh[z];
    const __half* Bl_g = cfg.Bl[z];
    const float* bias  = cfg.bias[z];
    const int mode     = cfg.mode[z];
    const float bsc    = cfg.bscale[z];
    const int K        = cfg.K;
    const int ldc      = cfg.ldc;

    const int tid = threadIdx.x;
    const int wid = tid >> 5;
    const int lane = tid & 31;
    const int g = lane >> 2;
    const int t = lane & 3;
    const int wm = wid & 3;
    const int wn = wid >> 2;
    const int col0 = blockIdx.x * 64;

    const int q8 = lane & 7;
    const int seg = lane >> 3;
    const uint32_t smem_base = (uint32_t)__cvta_generic_to_shared(hsm);
    const uint32_t a_off = (uint32_t)((q8 + (seg & 1) * 8) * HAS + (seg >> 1) * 8);
    const uint32_t b_off = (uint32_t)((q8 + (seg >> 1) * 8) * HAS + (seg & 1) * 8);

    float dm[2][4][4];
    #pragma unroll
    for (int mt = 0; mt < 2; mt++)
        #pragma unroll
        for (int nt = 0; nt < 4; nt++)
            #pragma unroll
            for (int j = 0; j < 4; j++) dm[mt][nt][j] = 0.f;

    const int ktiles = K >> 5;

    #pragma unroll
    for (int p = 0; p < 2; p++) {
        __half* Ahs = hsm + p * HSTAGE;
        __half* Bhs = Ahs + G_A * HAS;
        __half* Bls = Bhs + G_B * HAS;
        int k0 = p << 5;
        #pragma unroll
        for (int i = 0; i < 2; i++) {
            int id = tid + 256 * i;
            int row = id >> 2, ch = id & 3;
            int r = row0 + row;
            int rc = r < M ? r : (M - 1);
            int pb = r < M ? 16 : 0;
            cp_async16((uint32_t)__cvta_generic_to_shared(&Ahs[row * HAS + ch * 8]),
                       &Ah_g[(size_t)rc * K + k0 + ch * 8], pb);
        }
        #pragma unroll
        for (int i = 0; i < 2; i++) {
            int id = tid + 256 * i;
            int arr = id >> 8, rem = id & 255;
            int row = rem >> 2, ch = rem & 3;
            const __half* src = (arr ? Bl_g : Bh_g) + (size_t)(col0 + row) * K + k0 + ch * 8;
            __half* dst = (arr ? Bls : Bhs) + row * HAS + ch * 8;
            cp_async16((uint32_t)__cvta_generic_to_shared(dst), src, 16);
        }
        cp_commit();
    }
    cp_wait<1>();
    __syncthreads();

    int cst = 0;

    for (int kt = 0; kt < ktiles; kt++) {
        const uint32_t stage = smem_base + (uint32_t)((cst * HSTAGE) * 2);

        #pragma unroll
        for (int ks = 0; ks < 2; ks++) {
            const uint32_t kb = (uint32_t)(ks * 16);
            uint32_t ah[2][4];
            #pragma unroll
            for (int mt = 0; mt < 2; mt++) {
                uint32_t rbase = (uint32_t)((wm * 32 + mt * 16) * HAS) + kb;
                ldsm_x4(ah[mt], stage + 2 * (rbase + a_off));
            }
            uint32_t bh[4][2], bl[4][2];
            #pragma unroll
            for (int p = 0; p < 2; p++) {
                uint32_t nbase = (uint32_t)((wn * 32 + p * 16) * HAS) + kb;
                uint32_t r4[4];
                ldsm_x4(r4, stage + 2 * (G_A * HAS + nbase + b_off));
                bh[2 * p][0] = r4[0]; bh[2 * p][1] = r4[1];
                bh[2 * p + 1][0] = r4[2]; bh[2 * p + 1][1] = r4[3];
                ldsm_x4(r4, stage + 2 * (G_A * HAS + G_B * HAS + nbase + b_off));
                bl[2 * p][0] = r4[0]; bl[2 * p][1] = r4[1];
                bl[2 * p + 1][0] = r4[2]; bl[2 * p + 1][1] = r4[3];
            }
            #pragma unroll
            for (int nt = 0; nt < 4; nt++) {
                #pragma unroll
                for (int mt = 0; mt < 2; mt++) {
                    mma_f16(dm[mt][nt], ah[mt][0], ah[mt][1], ah[mt][2], ah[mt][3], bh[nt][0], bh[nt][1]);
                    mma_f16(dm[mt][nt], ah[mt][0], ah[mt][1], ah[mt][2], ah[mt][3], bl[nt][0], bl[nt][1]);
                }
            }
        }

        int nk = kt + 2;
        if (nk < ktiles) {
            int st = nk % 3;
            __half* Ahs = hsm + st * HSTAGE;
            __half* Bhs = Ahs + G_A * HAS;
            __half* Bls = Bhs + G_B * HAS;
            int k0 = nk << 5;
            #pragma unroll
            for (int i = 0; i < 2; i++) {
                int id = tid + 256 * i;
                int row = id >> 2, ch = id & 3;
                int r = row0 + row;
                int rc = r < M ? r : (M - 1);
                int pb = r < M ? 16 : 0;
                cp_async16((uint32_t)__cvta_generic_to_shared(&Ahs[row * HAS + ch * 8]),
                           &Ah_g[(size_t)rc * K + k0 + ch * 8], pb);
            }
            #pragma unroll
            for (int i = 0; i < 2; i++) {
                int id = tid + 256 * i;
                int arr = id >> 8, rem = id & 255;
                int row = rem >> 2, ch = rem & 3;
                const __half* src = (arr ? Bl_g : Bh_g) + (size_t)(col0 + row) * K + k0 + ch * 8;
                __half* dst = (arr ? Bls : Bhs) + row * HAS + ch * 8;
                cp_async16((uint32_t)__cvta_generic_to_shared(dst), src, 16);
            }
        }
        cp_commit();
        cp_wait<1>();
        __syncthreads();

        cst = (cst == 2) ? 0 : cst + 1;
    }

    #pragma unroll
    for (int mt = 0; mt < 2; mt++) {
        #pragma unroll
        for (int nt = 0; nt < 4; nt++) {
            int r = row0 + wm * 32 + mt * 16 + g;
            int c = col0 + wn * 32 + nt * 8 + 2 * t;
            float2 bz = *(const float2*)&bias[c];
            float o0 = dm[mt][nt][0] + bsc * bz.x;
            float o1 = dm[mt][nt][1] + bsc * bz.y;
            float o2 = dm[mt][nt][2] + bsc * bz.x;
            float o3 = dm[mt][nt][3] + bsc * bz.y;
            if (mode == 0) {
                float* Cf = cfg.Cf[z];
                if (r < M)     *(float2*)&Cf[(size_t)r * ldc + c] = make_float2(o0, o1);
                if (r + 8 < M) *(float2*)&Cf[(size_t)(r + 8) * ldc + c] = make_float2(o2, o3);
            } else if (mode == 1) {
                __half* Ch = cfg.Ch[z];
                __half* Cl = cfg.Cl[z];
                __half h0, l0, h1, l1;
                if (r < M) {
                    split_h(o0, h0, l0); split_h(o1, h1, l1);
                    *(__half2*)&Ch[(size_t)r * ldc + c] = __halves2half2(h0, h1);
                    *(__half2*)&Cl[(size_t)r * ldc + c] = __halves2half2(l0, l1);
                }
                if (r + 8 < M) {
                    split_h(o2, h0, l0); split_h(o3, h1, l1);
                    *(__half2*)&Ch[(size_t)(r + 8) * ldc + c] = __halves2half2(h0, h1);
                    *(__half2*)&Cl[(size_t)(r + 8) * ldc + c] = __halves2half2(l0, l1);
                }
            } else {
                __half* Ch = cfg.Ch[z];
                if (r < M)
                    *(__half2*)&Ch[(size_t)r * ldc + c] =
                        __halves2half2(__float2half_rn(o0), __float2half_rn(o1));
                if (r + 8 < M)
                    *(__half2*)&Ch[(size_t)(r + 8) * ldc + c] =
                        __halves2half2(__float2half_rn(o2), __float2half_rn(o3));
            }
        }
    }
}

// ---------------- sentence-level graph attention (8 threads/row) ----------------
__global__ __launch_bounds__(256) void sent_attn8(
    const float* __restrict__ qs, const float* __restrict__ ksn,
    const float* __restrict__ vsn, const float* __restrict__ bias_s,
    const float* __restrict__ gab,
    float* __restrict__ attns_out,
    __half* __restrict__ csh)
{
    const int h = blockIdx.x, b = blockIdx.y;
    const int q0 = blockIdx.z * 32;
    const int tid = threadIdx.x;
    const int row = tid >> 3;
    const int sub = tid & 7;
    const int q = q0 + row;

    __shared__ float Ks[NSd][DKd + 1];
    __shared__ float Vs[NSd][DKd + 1];
    __shared__ float G[NSd][NSd + 1];
    __shared__ float Att[32][NSd + 1];

    for (int idx = tid; idx < NSd * DKd; idx += 256) {
        int s = idx >> 6, k = idx & 63;
        Ks[s][k] = ksn[(size_t)(b * NSd + s) * Dd + h * DKd + k];
        Vs[s][k] = vsn[(size_t)(b * NSd + s) * Dd + h * DKd + k];
    }
    for (int idx = tid; idx < NSd * NSd; idx += 256) {
        int s = idx / NSd, tt = idx % NSd;
        G[s][tt] = gab[((size_t)(b * Hd + h) * NSd + s) * NSd + tt];
    }
    __syncthreads();

    float qreg[8];
    const float* qrow = qs + (size_t)(b * LQd + q) * Dd + h * DKd + sub * 8;
    #pragma unroll
    for (int k = 0; k < 8; k++) qreg[k] = qrow[k] * 0.125f;

    float a[NSd];
    #pragma unroll
    for (int s = 0; s < NSd; s++) {
        float dd = 0.f;
        #pragma unroll
        for (int k = 0; k < 8; k++) dd += qreg[k] * Ks[s][sub * 8 + k];
        a[s] = dd;
    }
    #pragma unroll
    for (int s = 0; s < NSd; s++) {
        a[s] += __shfl_xor_sync(0xffffffffu, a[s], 1);
        a[s] += __shfl_xor_sync(0xffffffffu, a[s], 2);
        a[s] += __shfl_xor_sync(0xffffffffu, a[s], 4);
    }
    const float* bsrow = bias_s + ((size_t)(b * Hd + h) * LQd + q) * NSd;
    #pragma unroll
    for (int s = 0; s < NSd; s++) a[s] += bsrow[s];

    float m = -1e30f;
    #pragma unroll
    for (int s = 0; s < NSd; s++) m = fmaxf(m, a[s]);
    float smx[NSd]; float sum = 0.f;
    #pragma unroll
    for (int s = 0; s < NSd; s++) { smx[s] = __expf(a[s] - m); sum += smx[s]; }
    float inv = 1.f / sum;

    const int t0 = sub * 3;
    float an[3];
    #pragma unroll
    for (int j = 0; j < 3; j++) {
        float dd = 0.f;
        #pragma unroll
        for (int s = 0; s < NSd; s++) dd += smx[s] * G[s][t0 + j];
        float gg = dd * inv;
        an[j] = a[t0 + j] - 0.5f * gg * gg;
    }

    float m2 = -1e30f;
    #pragma unroll
    for (int j = 0; j < 3; j++) m2 = fmaxf(m2, an[j]);
    m2 = fmaxf(m2, __shfl_xor_sync(0xffffffffu, m2, 1));
    m2 = fmaxf(m2, __shfl_xor_sync(0xffffffffu, m2, 2));
    m2 = fmaxf(m2, __shfl_xor_sync(0xffffffffu, m2, 4));
    float e[3]; float su = 0.f;
    #pragma unroll
    for (int j = 0; j < 3; j++) { e[j] = __expf(an[j] - m2); su += e[j]; }
    su += __shfl_xor_sync(0xffffffffu, su, 1);
    su += __shfl_xor_sync(0xffffffffu, su, 2);
    su += __shfl_xor_sync(0xffffffffu, su, 4);
    float inv2 = 1.f / su;

    float* arow = attns_out + ((size_t)(b * Hd + h) * LQd + q) * NSd;
    #pragma unroll
    for (int j = 0; j < 3; j++) {
        float v = e[j] * inv2;
        Att[row][t0 + j] = v;
        arow[t0 + j] = v;
    }
    __syncwarp();

    float att[NSd];
    #pragma unroll
    for (int s = 0; s < NSd; s++) att[s] = Att[row][s];

    size_t cbase = (size_t)(b * LQd + q) * Dd + h * DKd + sub * 8;
    #pragma unroll
    for (int dd = 0; dd < 8; dd++) {
        float acc = 0.f;
        #pragma unroll
        for (int s = 0; s < NSd; s++) acc += att[s] * Vs[s][sub * 8 + dd];
        csh[cbase + dd] = __float2half_rn(acc);
    }
}

// ---------------- word-level attention v7: split K/V pipelining + bias hoist ----------------
#define HQS 72
#define W_QH 0
#define W_KV (32 * HQS)
#define W_ARR (128 * HQS)
#define W_P  (W_KV + 4 * W_ARR)
#define PROW 264
#define WSMEM_BYTES ((W_P + 32 * PROW) * 2)

__global__ __launch_bounds__(512, 2) void word_attn_h7(
    const __half* __restrict__ qwh,
    const __half* __restrict__ kwh, const __half* __restrict__ kwl,
    const __half* __restrict__ vwh, const __half* __restrict__ vwl,
    const float* __restrict__ bias_w, const float* __restrict__ attns,
    __half* __restrict__ cwh)
{
    extern __shared__ __half hsm[];
    float* Ps = (float*)(hsm + W_P);
    __half* PU = hsm + W_P;

    const int tid = threadIdx.x;
    const int wid = tid >> 5;
    const int lane = tid & 31;
    const int g = lane >> 2;
    const int t = lane & 3;
    const int wm = wid & 1;
    const int wn = wid >> 1;
    const int q0 = blockIdx.x * 32;
    const int h  = blockIdx.y;
    const int b  = blockIdx.z;

    const int q8 = lane & 7;
    const int seg = lane >> 3;
    const uint32_t smem_base = (uint32_t)__cvta_generic_to_shared(hsm);
    const uint32_t aq_off = (uint32_t)((q8 + (seg & 1) * 8) * HQS + (seg >> 1) * 8);
    const uint32_t bk_off = (uint32_t)((q8 + (seg >> 1) * 8) * HQS + (seg & 1) * 8);
    const uint32_t ap_off = (uint32_t)((q8 + (seg & 1) * 8) * PROW + (seg >> 1) * 8);
    const uint32_t v_arr  = (seg >> 1) ? (uint32_t)(W_KV + 3 * W_ARR) : (uint32_t)(W_KV + 2 * W_ARR);
    const uint32_t v_off  = (uint32_t)((q8 + (seg & 1) * 8) * HQS + wn * 8);

    {
        if (tid < 256) {
            int row = tid >> 3, ch = tid & 7;
            const __half* src = qwh + (size_t)(b * LQd + q0 + row) * Dd + h * DKd + ch * 8;
            cp_async16((uint32_t)__cvta_generic_to_shared(&hsm[W_QH + row * HQS + ch * 8]),
                       src, 16);
        }
        const size_t kvb = (size_t)(b * NSd) * NTd * Dd + h * DKd;
        const __half* srcs[4] = {kwh, kwl, vwh, vwl};
        #pragma unroll
        for (int i = 0; i < 8; i++) {
            int id = tid + 512 * i;
            int arr = id >> 10, rem = id & 1023;
            int row = rem >> 3, ch = rem & 7;
            const __half* src = srcs[arr] + kvb + (size_t)row * Dd + ch * 8;
            cp_async16((uint32_t)__cvta_generic_to_shared(
                           &hsm[W_KV + arr * W_ARR + row * HQS + ch * 8]),
                       src, 16);
        }
        cp_commit();
        cp_wait<0>();
    }
    __syncthreads();

    float om[4], oc[4];
    #pragma unroll
    for (int j = 0; j < 4; j++) { om[j] = 0.f; oc[j] = 0.f; }

    for (int s = 0; s < NSd; s++) {
        // hoist bias_w + attns loads for this s (consumed in softmax; overlap QK)
        const float* bb = bias_w + ((size_t)((b * NSd + s) * Hd + h) * LQd + q0) * NTd;
        float bld[2][4], ald[2];
        #pragma unroll
        for (int rr = 0; rr < 2; rr++) {
            int r = wid * 2 + rr;
            bld[rr][0] = bb[r * NTd + lane];
            bld[rr][1] = bb[r * NTd + lane + 32];
            bld[rr][2] = bb[r * NTd + lane + 64];
            bld[rr][3] = bb[r * NTd + lane + 96];
            ald[rr] = attns[((size_t)(b * Hd + h) * LQd + q0 + r) * NSd + s];
        }

        // ---- QK ----
        float pm[2][4], pc[2][4];
        #pragma unroll
        for (int nt = 0; nt < 2; nt++)
            #pragma unroll
            for (int j = 0; j < 4; j++) { pm[nt][j] = 0.f; pc[nt][j] = 0.f; }

        #pragma unroll
        for (int ks = 0; ks < 4; ks++) {
            const uint32_t kb = (uint32_t)(ks * 16);
            uint32_t ahq[4], kh4[4], kl4[4];
            uint32_t qrb = (uint32_t)(wm * 16 * HQS) + kb;
            ldsm_x4(ahq, smem_base + 2 * (W_QH + qrb + aq_off));
            uint32_t krb = (uint32_t)(wn * 16 * HQS) + kb;
            ldsm_x4(kh4, smem_base + 2 * (W_KV + krb + bk_off));
            ldsm_x4(kl4, smem_base + 2 * (W_KV + W_ARR + krb + bk_off));
            #pragma unroll
            for (int nt = 0; nt < 2; nt++) {
                mma_f16(pm[nt], ahq[0], ahq[1], ahq[2], ahq[3], kh4[2 * nt], kh4[2 * nt + 1]);
                mma_f16(pc[nt], ahq[0], ahq[1], ahq[2], ahq[3], kl4[2 * nt], kl4[2 * nt + 1]);
            }
        }
        #pragma unroll
        for (int nt = 0; nt < 2; nt++) {
            int r = wm * 16 + g;
            int c = wn * 16 + nt * 8 + 2 * t;
            *(float2*)&Ps[r * 132 + c] = make_float2(pm[nt][0] + pc[nt][0], pm[nt][1] + pc[nt][1]);
            *(float2*)&Ps[(r + 8) * 132 + c] = make_float2(pm[nt][2] + pc[nt][2], pm[nt][3] + pc[nt][3]);
        }
        __syncthreads();   // Ps visible; K[s] dead

        // issue K(s+1)
        if (s + 1 < NSd) {
            const size_t kvb = (size_t)(b * NSd + s + 1) * NTd * Dd + h * DKd;
            const __half* srcs[2] = {kwh, kwl};
            #pragma unroll
            for (int i = 0; i < 4; i++) {
                int id = tid + 512 * i;
                int arr = id >> 10, rem = id & 1023;
                int row = rem >> 3, ch = rem & 7;
                const __half* src = srcs[arr] + kvb + (size_t)row * Dd + ch * 8;
                cp_async16((uint32_t)__cvta_generic_to_shared(
                               &hsm[W_KV + arr * W_ARR + row * HQS + ch * 8]),
                           src, 16);
            }
            cp_commit();
        }

        // ---- softmax (bias/attns already in registers) ----
        #pragma unroll
        for (int rr = 0; rr < 2; rr++) {
            int r = wid * 2 + rr;
            float x0 = Ps[r * 132 + lane]       + bld[rr][0];
            float x1 = Ps[r * 132 + lane + 32]  + bld[rr][1];
            float x2 = Ps[r * 132 + lane + 64]  + bld[rr][2];
            float x3 = Ps[r * 132 + lane + 96]  + bld[rr][3];
            float mx = fmaxf(fmaxf(x0, x1), fmaxf(x2, x3));
            #pragma unroll
            for (int o = 16; o; o >>= 1) mx = fmaxf(mx, __shfl_xor_sync(0xffffffffu, mx, o));
            x0 = __expf(x0 - mx); x1 = __expf(x1 - mx);
            x2 = __expf(x2 - mx); x3 = __expf(x3 - mx);
            float su = x0 + x1 + x2 + x3;
            #pragma unroll
            for (int o = 16; o; o >>= 1) su += __shfl_xor_sync(0xffffffffu, su, o);
            float wsc = ald[rr] / su;
            __half h0 = __float2half_rn(x0 * wsc);
            __half h1 = __float2half_rn(x1 * wsc);
            __half h2 = __float2half_rn(x2 * wsc);
            __half h3 = __float2half_rn(x3 * wsc);
            __syncwarp();
            __half* prow = PU + r * PROW;
            prow[lane]       = h0;
            prow[lane + 32]  = h1;
            prow[lane + 64]  = h2;
            prow[lane + 96]  = h3;
        }
        if (s > 0) cp_wait<1>();
        __syncthreads();   // PU visible; V[s] visible

        // ---- PV ----
        #pragma unroll
        for (int ks = 0; ks < 8; ks++) {
            const uint32_t kb = (uint32_t)(ks * 16);
            uint32_t ph4[4], v4[4];
            uint32_t prb = (uint32_t)(wm * 16 * PROW) + kb;
            ldsm_x4(ph4, smem_base + 2 * (W_P + prb + ap_off));
            ldsm_x4_t(v4, smem_base + 2 * (v_arr + kb * HQS + v_off));
            mma_f16(om, ph4[0], ph4[1], ph4[2], ph4[3], v4[0], v4[1]);
            mma_f16(oc, ph4[0], ph4[1], ph4[2], ph4[3], v4[2], v4[3]);
        }

        if (s + 1 < NSd) {
            __syncthreads();   // V[s] dead
            const size_t kvb = (size_t)(b * NSd + s + 1) * NTd * Dd + h * DKd;
            const __half* srcs[2] = {vwh, vwl};
            #pragma unroll
            for (int i = 0; i < 4; i++) {
                int id = tid + 512 * i;
                int arr = id >> 10, rem = id & 1023;
                int row = rem >> 3, ch = rem & 7;
                const __half* src = srcs[arr] + kvb + (size_t)row * Dd + ch * 8;
                cp_async16((uint32_t)__cvta_generic_to_shared(
                               &hsm[W_KV + (2 + arr) * W_ARR + row * HQS + ch * 8]),
                           src, 16);
            }
            cp_commit();
            cp_wait<1>();
            __syncthreads();   // K(s+1) visible
        }
    }

    {
        int r = q0 + wm * 16 + g;
        int c = h * DKd + wn * 8 + 2 * t;
        float v0 = om[0] + oc[0], v1 = om[1] + oc[1];
        float v2 = om[2] + oc[2], v3 = om[3] + oc[3];
        *(__half2*)&cwh[(size_t)(b * LQd + r) * Dd + c] =
            __halves2half2(__float2half_rn(v0), __float2half_rn(v1));
        *(__half2*)&cwh[(size_t)(b * LQd + r + 8) * Dd + c] =
            __halves2half2(__float2half_rn(v2), __float2half_rn(v3));
    }
}

// ---------------- host ----------------
extern "C" void kernel_launch(void* const* d_in, const int* in_sizes, int n_in,
                              void* d_out, int out_size)
{
    const float* q      = (const float*)d_in[0];
    const float* k_s    = (const float*)d_in[1];
    const float* v_s    = (const float*)d_in[2];
    const float* k_w    = (const float*)d_in[3];
    const float* v_w    = (const float*)d_in[4];
    const float* bias_w = (const float*)d_in[5];
    const float* bias_s = (const float*)d_in[6];
    const float* gab    = (const float*)d_in[7];

    const float *wq_s, *bq_s, *wk_s, *bk_s, *wv_s, *bv_s;
    const float *wq_w, *bq_w, *wk_w, *bk_w, *wv_w, *bv_w;
    const float *fcs_w, *fcs_b, *fcw_w, *fcw_b, *fco_w, *fco_b;

    if (in_sizes[9] == 512) {
        wq_s = (const float*)d_in[8];  bq_s = (const float*)d_in[9];
        wk_s = (const float*)d_in[10]; bk_s = (const float*)d_in[11];
        wv_s = (const float*)d_in[12]; bv_s = (const float*)d_in[13];
        wq_w = (const float*)d_in[14]; bq_w = (const float*)d_in[15];
        wk_w = (const float*)d_in[16]; bk_w = (const float*)d_in[17];
        wv_w = (const float*)d_in[18]; bv_w = (const float*)d_in[19];
        fcs_w = (const float*)d_in[20]; fcs_b = (const float*)d_in[21];
        fcw_w = (const float*)d_in[22]; fcw_b = (const float*)d_in[23];
        fco_w = (const float*)d_in[24]; fco_b = (const float*)d_in[25];
    } else {
        wq_s = (const float*)d_in[8];  wk_s = (const float*)d_in[9];
        wv_s = (const float*)d_in[10]; wq_w = (const float*)d_in[11];
        wk_w = (const float*)d_in[12]; wv_w = (const float*)d_in[13];
        fcs_w = (const float*)d_in[14]; fcw_w = (const float*)d_in[15];
        bq_s = (const float*)d_in[16]; bk_s = (const float*)d_in[17];
        bv_s = (const float*)d_in[18]; bq_w = (const float*)d_in[19];
        bk_w = (const float*)d_in[20]; bv_w = (const float*)d_in[21];
        fcs_b = (const float*)d_in[22]; fcw_b = (const float*)d_in[23];
        fco_w = (const float*)d_in[24]; fco_b = (const float*)d_in[25];
    }

    float* scratch = nullptr;
    cudaGetSymbolAddress((void**)&scratch, g_scratch);
    float* s_qs  = scratch + OFF_QS;
    float* s_ks  = scratch + OFF_KS;
    float* s_vs  = scratch + OFF_VS;
    float* s_att = scratch + OFF_ATT;
    __half* hb = (__half*)(scratch + OFF_HALF);
    __half* acth = hb + H_ACTH;
    __half* wth  = hb + H_WTH;
    __half* wtl  = hb + H_WTL;
    __half* qwh  = hb + H_QWH;
    __half* kwh  = hb + H_KWH;
    __half* kwl  = hb + H_KWL;
    __half* vwh  = hb + H_VWH;
    __half* vwl  = hb + H_VWL;
    __half* csh  = hb + H_CSH;
    __half* cwh  = hb + H_CWH;
    __half* cath = hb + H_CATH;

    cudaFuncSetAttribute(gemm_cfg, cudaFuncAttributeMaxDynamicSharedMemorySize, HSMEM_BYTES);
    cudaFuncSetAttribute(word_attn_h7, cudaFuncAttributeMaxDynamicSharedMemorySize, WSMEM_BYTES);

    // prep
    ASplitArgs aa;
    aa.src[0] = q; aa.src[1] = k_s; aa.src[2] = v_s; aa.src[3] = k_w; aa.src[4] = v_w;
    act_split<<<dim3(256, 5), 256>>>(aa, acth);
    WSplitArgs wa;
    wa.src[0] = wq_s; wa.src[1] = wk_s; wa.src[2] = wv_s;
    wa.src[3] = wq_w; wa.src[4] = wk_w; wa.src[5] = wv_w;
    wa.src[6] = fcs_w; wa.src[7] = fcw_w; wa.src[8] = fco_w;
    w_transplit<<<dim3(16, 32, 9), dim3(32, 8)>>>(wa, wth, wtl);

    // all projections in ONE launch
    {
        GemmCfg c = {};
        c.K = 512; c.ldc = 512;
        c.Ah[0] = acth + AKW; c.Bh[0] = wth + WOFF(4); c.Bl[0] = wtl + WOFF(4);
        c.Ah[1] = acth + AVW; c.Bh[1] = wth + WOFF(5); c.Bl[1] = wtl + WOFF(5);
        c.Ah[2] = acth + AQ;  c.Bh[2] = wth + WOFF(0); c.Bl[2] = wtl + WOFF(0);
        c.Ah[3] = acth + AQ;  c.Bh[3] = wth + WOFF(3); c.Bl[3] = wtl + WOFF(3);
        c.Ah[4] = acth + AKS; c.Bh[4] = wth + WOFF(1); c.Bl[4] = wtl + WOFF(1);
        c.Ah[5] = acth + AVS; c.Bh[5] = wth + WOFF(2); c.Bl[5] = wtl + WOFF(2);
        c.bias[0] = bk_w; c.bias[1] = bv_w; c.bias[2] = bq_s;
        c.bias[3] = bq_w; c.bias[4] = bk_s; c.bias[5] = bv_s;
        c.bscale[0] = 1.f; c.bscale[1] = 1.f; c.bscale[2] = 1.f;
        c.bscale[3] = 0.125f; c.bscale[4] = 1.f; c.bscale[5] = 1.f;
        c.M[0] = 12288; c.M[1] = 12288; c.M[2] = 1024;
        c.M[3] = 1024;  c.M[4] = 96;    c.M[5] = 96;
        c.mode[0] = 1; c.mode[1] = 1; c.mode[2] = 0;
        c.mode[3] = 2; c.mode[4] = 0; c.mode[5] = 0;
        c.Ch[0] = kwh; c.Cl[0] = kwl;
        c.Ch[1] = vwh; c.Cl[1] = vwl;
        c.Cf[2] = s_qs;
        c.Ch[3] = qwh;
        c.Cf[4] = s_ks;
        c.Cf[5] = s_vs;
        gemm_cfg<<<dim3(8, 96, 6), 256, HSMEM_BYTES>>>(c);
    }

    sent_attn8<<<dim3(Hd, BB, 8), 256>>>(s_qs, s_ks, s_vs, bias_s, gab, s_att, csh);

    word_attn_h7<<<dim3(8, Hd, BB), 512, WSMEM_BYTES>>>(
        qwh, kwh, kwl, vwh, vwl, bias_w, s_att, cwh);

    // fcs / fcw -> fp16 cat (hi only; fco reads only cath)
    {
        GemmCfg c = {};
        c.K = 512; c.ldc = 1024;
        c.Ah[0] = csh; c.Bh[0] = wth + WOFF(6); c.Bl[0] = wtl + WOFF(6);
        c.Ah[1] = cwh; c.Bh[1] = wth + WOFF(7); c.Bl[1] = wtl + WOFF(7);
        c.bias[0] = fcs_b; c.bias[1] = fcw_b;
        c.bscale[0] = 1.f; c.bscale[1] = 1.f;
        c.M[0] = 1024; c.M[1] = 1024;
        c.mode[0] = 2; c.mode[1] = 2;
        c.Ch[0] = cath;
        c.Ch[1] = cath + 512;
        gemm_cfg<<<dim3(8, 8, 2), 256, HSMEM_BYTES>>>(c);
    }
    // final fco -> fp32 out
    {
        GemmCfg c = {};
        c.K = 1024; c.ldc = 512;
        c.Ah[0] = cath; c.Bh[0] = wth + WOFF(8); c.Bl[0] = wtl + WOFF(8);
        c.bias[0] = fco_b;
        c.bscale[0] = 1.f;
        c.M[0] = 1024;
        c.mode[0] = 0;
        c.Cf[0] = (float*)d_out;
        gemm_cfg<<<dim3(8, 8, 1), 256, HSMEM_BYTES>>>(c);
    }
}

// round 16
// speedup vs baseline: 1.0322x; 1.0322x over previous
#include <cuda_runtime.h>
#include <cuda_fp16.h>
#include <math.h>
#include <stdint.h>

// Problem constants
#define BB   4
#define LQd  256
#define NSd  24
#define NTd  128
#define Dd   512
#define Hd   8
#define DKd  64

// ---------------- scratch layout ----------------
#define OFF_QS   0
#define OFF_KS   524288
#define OFF_VS   573440
#define OFF_ATT  622592
#define OFF_HALF 819200
#define H_ACTH 0
#define H_ACTL 13205504
#define H_WTH  26411008
#define H_WTL  29032448
#define H_QWH  31653888
#define H_QWL  32178176
#define H_KWH  32702464
#define H_KWL  38993920
#define H_VWH  45285376
#define H_VWL  51576832
#define H_CSH  57868288
#define H_CSL  58392576
#define H_CWH  58916864
#define H_CWL  59441152
#define H_CATH 59965440
#define H_CATL 61014016
#define H_TOTAL 62062592
#define SCRATCH_TOTAL (OFF_HALF + H_TOTAL / 2)
__device__ float g_scratch[SCRATCH_TOTAL];

#define AQ   0
#define AKS  524288
#define AVS  573440
#define AKW  622592
#define AVW  6914048
#define WOFF(i) ((i) * 262144)

// ---------------- helpers ----------------
__device__ __forceinline__ void split_h(float x, __half& hi, __half& lo) {
    hi = __float2half_rn(x);
    lo = __float2half_rn(x - __half2float(hi));
}
__device__ __forceinline__ void mma_f16(float d[4],
                                        uint32_t a0, uint32_t a1, uint32_t a2, uint32_t a3,
                                        uint32_t b0, uint32_t b1) {
    asm volatile(
        "mma.sync.aligned.m16n8k16.row.col.f32.f16.f16.f32 "
        "{%0,%1,%2,%3},{%4,%5,%6,%7},{%8,%9},{%0,%1,%2,%3};"
        : "+f"(d[0]), "+f"(d[1]), "+f"(d[2]), "+f"(d[3])
        : "r"(a0), "r"(a1), "r"(a2), "r"(a3), "r"(b0), "r"(b1));
}
__device__ __forceinline__ void ldsm_x4(uint32_t r[4], uint32_t addr) {
    asm volatile("ldmatrix.sync.aligned.m8n8.x4.shared.b16 {%0,%1,%2,%3}, [%4];"
                 : "=r"(r[0]), "=r"(r[1]), "=r"(r[2]), "=r"(r[3]) : "r"(addr));
}
__device__ __forceinline__ void ldsm_x4_t(uint32_t r[4], uint32_t addr) {
    asm volatile("ldmatrix.sync.aligned.m8n8.x4.trans.shared.b16 {%0,%1,%2,%3}, [%4];"
                 : "=r"(r[0]), "=r"(r[1]), "=r"(r[2]), "=r"(r[3]) : "r"(addr));
}
__device__ __forceinline__ void cp_async16(uint32_t smem_addr, const void* gptr, int src_bytes) {
    asm volatile("cp.async.cg.shared.global [%0], [%1], 16, %2;"
                 :: "r"(smem_addr), "l"(gptr), "r"(src_bytes) : "memory");
}
__device__ __forceinline__ void cp_commit() { asm volatile("cp.async.commit_group;" ::: "memory"); }
template <int N>
__device__ __forceinline__ void cp_wait() { asm volatile("cp.async.wait_group %0;" :: "n"(N) : "memory"); }

// ---------------- prep: convert activations to fp16 ----------------
struct ASplitArgs { const float* src[5]; };
__constant__ int c_alen[5] = {524288, 49152, 49152, 6291456, 6291456};
__constant__ int c_aoff[5] = {AQ, AKS, AVS, AKW, AVW};

__global__ __launch_bounds__(256) void act_split(ASplitArgs args, __half* acth)
{
    int z = blockIdx.y;
    int n = c_alen[z];
    const float* s = args.src[z];
    __half* dh = acth + c_aoff[z];
    for (int i = blockIdx.x * 256 + threadIdx.x; i < n; i += gridDim.x * 256) {
        dh[i] = __float2half_rn(s[i]);
    }
}

// ---------------- prep: transpose+split weights ----------------
struct WSplitArgs { const float* src[9]; };
__constant__ int c_wK[9] = {512, 512, 512, 512, 512, 512, 512, 512, 1024};
__constant__ int c_woff[9] = {WOFF(0), WOFF(1), WOFF(2), WOFF(3), WOFF(4),
                              WOFF(5), WOFF(6), WOFF(7), WOFF(8)};
__constant__ float c_wscale[9] = {1.f, 1.f, 1.f, 0.125f, 1.f, 1.f, 1.f, 1.f, 1.f};

__global__ void w_transplit(WSplitArgs args, __half* wth, __half* wtl)
{
    int z = blockIdx.z;
    int Kw = c_wK[z];
    int k0 = blockIdx.y * 32;
    if (k0 >= Kw) return;
    int n0 = blockIdx.x * 32;
    const float* W = args.src[z];
    float sc = c_wscale[z];
    __half* th = wth + c_woff[z];
    __half* tl = wtl + c_woff[z];

    __shared__ float ts[32][33];
    int tx = threadIdx.x, ty = threadIdx.y;
    #pragma unroll
    for (int r = 0; r < 4; r++)
        ts[ty + 8 * r][tx] = W[(size_t)(k0 + ty + 8 * r) * 512 + n0 + tx];
    __syncthreads();
    #pragma unroll
    for (int r = 0; r < 4; r++) {
        int n = n0 + ty + 8 * r;
        int k = k0 + tx;
        __half hi, lo;
        split_h(sc * ts[tx][ty + 8 * r], hi, lo);
        th[(size_t)n * Kw + k] = hi;
        tl[(size_t)n * Kw + k] = lo;
    }
}

// ---------------- 2-term GEMM: A fp16, B split hi/lo, 3-stage pipeline ----------------
// mode: 0 = fp32 out, 1 = split fp16 hi+lo out, 2 = fp16 hi only
#define HAS 40
#define G_A 128
#define G_B 64
#define HSTAGE ((G_A + 2 * G_B) * HAS)
#define HSMEM_BYTES (3 * HSTAGE * 2)

struct GemmCfg {
    const __half* Ah[6];
    const __half* Bh[6]; const __half* Bl[6];
    const float* bias[6];
    float* Cf[6];
    __half* Ch[6]; __half* Cl[6];
    int M[6]; int mode[6]; float bscale[6];
    int K; int ldc;
};

__global__ __launch_bounds__(256, 2) void gemm_cfg(GemmCfg cfg)
{
    extern __shared__ __half hsm[];

    const int z = blockIdx.z;
    const int M = cfg.M[z];
    const int row0 = blockIdx.y * 128;
    if (row0 >= M) return;

    const __half* Ah_g = cfg.Ah[z];
    const __half* Bh_g = cfg.Bh[z];
    const __half* Bl_g = cfg.Bl[z];
    const float* bias  = cfg.bias[z];
    const int mode     = cfg.mode[z];
    const float bsc    = cfg.bscale[z];
    const int K        = cfg.K;
    const int ldc      = cfg.ldc;

    const int tid = threadIdx.x;
    const int wid = tid >> 5;
    const int lane = tid & 31;
    const int g = lane >> 2;
    const int t = lane & 3;
    const int wm = wid & 3;
    const int wn = wid >> 2;
    const int col0 = blockIdx.x * 64;

    const int q8 = lane & 7;
    const int seg = lane >> 3;
    const uint32_t smem_base = (uint32_t)__cvta_generic_to_shared(hsm);
    const uint32_t a_off = (uint32_t)((q8 + (seg & 1) * 8) * HAS + (seg >> 1) * 8);
    const uint32_t b_off = (uint32_t)((q8 + (seg >> 1) * 8) * HAS + (seg & 1) * 8);

    float dm[2][4][4], dc[2][4][4];
    #pragma unroll
    for (int mt = 0; mt < 2; mt++)
        #pragma unroll
        for (int nt = 0; nt < 4; nt++)
            #pragma unroll
            for (int j = 0; j < 4; j++) { dm[mt][nt][j] = 0.f; dc[mt][nt][j] = 0.f; }

    const int ktiles = K >> 5;

    #pragma unroll
    for (int p = 0; p < 2; p++) {
        __half* Ahs = hsm + p * HSTAGE;
        __half* Bhs = Ahs + G_A * HAS;
        __half* Bls = Bhs + G_B * HAS;
        int k0 = p << 5;
        #pragma unroll
        for (int i = 0; i < 2; i++) {
            int id = tid + 256 * i;
            int row = id >> 2, ch = id & 3;
            int r = row0 + row;
            int rc = r < M ? r : (M - 1);
            int pb = r < M ? 16 : 0;
            cp_async16((uint32_t)__cvta_generic_to_shared(&Ahs[row * HAS + ch * 8]),
                       &Ah_g[(size_t)rc * K + k0 + ch * 8], pb);
        }
        #pragma unroll
        for (int i = 0; i < 2; i++) {
            int id = tid + 256 * i;
            int arr = id >> 8, rem = id & 255;
            int row = rem >> 2, ch = rem & 3;
            const __half* src = (arr ? Bl_g : Bh_g) + (size_t)(col0 + row) * K + k0 + ch * 8;
            __half* dst = (arr ? Bls : Bhs) + row * HAS + ch * 8;
            cp_async16((uint32_t)__cvta_generic_to_shared(dst), src, 16);
        }
        cp_commit();
    }
    cp_wait<1>();
    __syncthreads();

    int cst = 0;

    for (int kt = 0; kt < ktiles; kt++) {
        const uint32_t stage = smem_base + (uint32_t)((cst * HSTAGE) * 2);

        #pragma unroll
        for (int ks = 0; ks < 2; ks++) {
            const uint32_t kb = (uint32_t)(ks * 16);
            uint32_t ah[2][4];
            #pragma unroll
            for (int mt = 0; mt < 2; mt++) {
                uint32_t rbase = (uint32_t)((wm * 32 + mt * 16) * HAS) + kb;
                ldsm_x4(ah[mt], stage + 2 * (rbase + a_off));
            }
            uint32_t bh[4][2], bl[4][2];
            #pragma unroll
            for (int p = 0; p < 2; p++) {
                uint32_t nbase = (uint32_t)((wn * 32 + p * 16) * HAS) + kb;
                uint32_t r4[4];
                ldsm_x4(r4, stage + 2 * (G_A * HAS + nbase + b_off));
                bh[2 * p][0] = r4[0]; bh[2 * p][1] = r4[1];
                bh[2 * p + 1][0] = r4[2]; bh[2 * p + 1][1] = r4[3];
                ldsm_x4(r4, stage + 2 * (G_A * HAS + G_B * HAS + nbase + b_off));
                bl[2 * p][0] = r4[0]; bl[2 * p][1] = r4[1];
                bl[2 * p + 1][0] = r4[2]; bl[2 * p + 1][1] = r4[3];
            }
            #pragma unroll
            for (int nt = 0; nt < 4; nt++) {
                #pragma unroll
                for (int mt = 0; mt < 2; mt++) {
                    mma_f16(dm[mt][nt], ah[mt][0], ah[mt][1], ah[mt][2], ah[mt][3], bh[nt][0], bh[nt][1]);
                    mma_f16(dc[mt][nt], ah[mt][0], ah[mt][1], ah[mt][2], ah[mt][3], bl[nt][0], bl[nt][1]);
                }
            }
        }

        int nk = kt + 2;
        if (nk < ktiles) {
            int st = nk % 3;
            __half* Ahs = hsm + st * HSTAGE;
            __half* Bhs = Ahs + G_A * HAS;
            __half* Bls = Bhs + G_B * HAS;
            int k0 = nk << 5;
            #pragma unroll
            for (int i = 0; i < 2; i++) {
                int id = tid + 256 * i;
                int row = id >> 2, ch = id & 3;
                int r = row0 + row;
                int rc = r < M ? r : (M - 1);
                int pb = r < M ? 16 : 0;
                cp_async16((uint32_t)__cvta_generic_to_shared(&Ahs[row * HAS + ch * 8]),
                           &Ah_g[(size_t)rc * K + k0 + ch * 8], pb);
            }
            #pragma unroll
            for (int i = 0; i < 2; i++) {
                int id = tid + 256 * i;
                int arr = id >> 8, rem = id & 255;
                int row = rem >> 2, ch = rem & 3;
                const __half* src = (arr ? Bl_g : Bh_g) + (size_t)(col0 + row) * K + k0 + ch * 8;
                __half* dst = (arr ? Bls : Bhs) + row * HAS + ch * 8;
                cp_async16((uint32_t)__cvta_generic_to_shared(dst), src, 16);
            }
        }
        cp_commit();
        cp_wait<1>();
        __syncthreads();

        cst = (cst == 2) ? 0 : cst + 1;
    }

    #pragma unroll
    for (int mt = 0; mt < 2; mt++) {
        #pragma unroll
        for (int nt = 0; nt < 4; nt++) {
            int r = row0 + wm * 32 + mt * 16 + g;
            int c = col0 + wn * 32 + nt * 8 + 2 * t;
            float2 bz = *(const float2*)&bias[c];
            float o0 = dm[mt][nt][0] + dc[mt][nt][0] + bsc * bz.x;
            float o1 = dm[mt][nt][1] + dc[mt][nt][1] + bsc * bz.y;
            float o2 = dm[mt][nt][2] + dc[mt][nt][2] + bsc * bz.x;
            float o3 = dm[mt][nt][3] + dc[mt][nt][3] + bsc * bz.y;
            if (mode == 0) {
                float* Cf = cfg.Cf[z];
                if (r < M)     *(float2*)&Cf[(size_t)r * ldc + c] = make_float2(o0, o1);
                if (r + 8 < M) *(float2*)&Cf[(size_t)(r + 8) * ldc + c] = make_float2(o2, o3);
            } else if (mode == 1) {
                __half* Ch = cfg.Ch[z];
                __half* Cl = cfg.Cl[z];
                __half h0, l0, h1, l1;
                if (r < M) {
                    split_h(o0, h0, l0); split_h(o1, h1, l1);
                    *(__half2*)&Ch[(size_t)r * ldc + c] = __halves2half2(h0, h1);
                    *(__half2*)&Cl[(size_t)r * ldc + c] = __halves2half2(l0, l1);
                }
                if (r + 8 < M) {
                    split_h(o2, h0, l0); split_h(o3, h1, l1);
                    *(__half2*)&Ch[(size_t)(r + 8) * ldc + c] = __halves2half2(h0, h1);
                    *(__half2*)&Cl[(size_t)(r + 8) * ldc + c] = __halves2half2(l0, l1);
                }
            } else {
                __half* Ch = cfg.Ch[z];
                if (r < M)
                    *(__half2*)&Ch[(size_t)r * ldc + c] =
                        __halves2half2(__float2half_rn(o0), __float2half_rn(o1));
                if (r + 8 < M)
                    *(__half2*)&Ch[(size_t)(r + 8) * ldc + c] =
                        __halves2half2(__float2half_rn(o2), __float2half_rn(o3));
            }
        }
    }
}

// ---------------- sentence-level graph attention (8 threads/row) ----------------
__global__ __launch_bounds__(256) void sent_attn8(
    const float* __restrict__ qs, const float* __restrict__ ksn,
    const float* __restrict__ vsn, const float* __restrict__ bias_s,
    const float* __restrict__ gab,
    float* __restrict__ attns_out,
    __half* __restrict__ csh)
{
    const int h = blockIdx.x, b = blockIdx.y;
    const int q0 = blockIdx.z * 32;
    const int tid = threadIdx.x;
    const int row = tid >> 3;
    const int sub = tid & 7;
    const int q = q0 + row;

    __shared__ float Ks[NSd][DKd + 1];
    __shared__ float Vs[NSd][DKd + 1];
    __shared__ float G[NSd][NSd + 1];
    __shared__ float Att[32][NSd + 1];

    for (int idx = tid; idx < NSd * DKd; idx += 256) {
        int s = idx >> 6, k = idx & 63;
        Ks[s][k] = ksn[(size_t)(b * NSd + s) * Dd + h * DKd + k];
        Vs[s][k] = vsn[(size_t)(b * NSd + s) * Dd + h * DKd + k];
    }
    for (int idx = tid; idx < NSd * NSd; idx += 256) {
        int s = idx / NSd, tt = idx % NSd;
        G[s][tt] = gab[((size_t)(b * Hd + h) * NSd + s) * NSd + tt];
    }
    __syncthreads();

    float qreg[8];
    const float* qrow = qs + (size_t)(b * LQd + q) * Dd + h * DKd + sub * 8;
    #pragma unroll
    for (int k = 0; k < 8; k++) qreg[k] = qrow[k] * 0.125f;

    float a[NSd];
    #pragma unroll
    for (int s = 0; s < NSd; s++) {
        float dd = 0.f;
        #pragma unroll
        for (int k = 0; k < 8; k++) dd += qreg[k] * Ks[s][sub * 8 + k];
        a[s] = dd;
    }
    #pragma unroll
    for (int s = 0; s < NSd; s++) {
        a[s] += __shfl_xor_sync(0xffffffffu, a[s], 1);
        a[s] += __shfl_xor_sync(0xffffffffu, a[s], 2);
        a[s] += __shfl_xor_sync(0xffffffffu, a[s], 4);
    }
    const float* bsrow = bias_s + ((size_t)(b * Hd + h) * LQd + q) * NSd;
    #pragma unroll
    for (int s = 0; s < NSd; s++) a[s] += bsrow[s];

    float m = -1e30f;
    #pragma unroll
    for (int s = 0; s < NSd; s++) m = fmaxf(m, a[s]);
    float smx[NSd]; float sum = 0.f;
    #pragma unroll
    for (int s = 0; s < NSd; s++) { smx[s] = __expf(a[s] - m); sum += smx[s]; }
    float inv = 1.f / sum;

    const int t0 = sub * 3;
    float an[3];
    #pragma unroll
    for (int j = 0; j < 3; j++) {
        float dd = 0.f;
        #pragma unroll
        for (int s = 0; s < NSd; s++) dd += smx[s] * G[s][t0 + j];
        float gg = dd * inv;
        an[j] = a[t0 + j] - 0.5f * gg * gg;
    }

    float m2 = -1e30f;
    #pragma unroll
    for (int j = 0; j < 3; j++) m2 = fmaxf(m2, an[j]);
    m2 = fmaxf(m2, __shfl_xor_sync(0xffffffffu, m2, 1));
    m2 = fmaxf(m2, __shfl_xor_sync(0xffffffffu, m2, 2));
    m2 = fmaxf(m2, __shfl_xor_sync(0xffffffffu, m2, 4));
    float e[3]; float su = 0.f;
    #pragma unroll
    for (int j = 0; j < 3; j++) { e[j] = __expf(an[j] - m2); su += e[j]; }
    su += __shfl_xor_sync(0xffffffffu, su, 1);
    su += __shfl_xor_sync(0xffffffffu, su, 2);
    su += __shfl_xor_sync(0xffffffffu, su, 4);
    float inv2 = 1.f / su;

    float* arow = attns_out + ((size_t)(b * Hd + h) * LQd + q) * NSd;
    #pragma unroll
    for (int j = 0; j < 3; j++) {
        float v = e[j] * inv2;
        Att[row][t0 + j] = v;
        arow[t0 + j] = v;
    }
    __syncwarp();

    float att[NSd];
    #pragma unroll
    for (int s = 0; s < NSd; s++) att[s] = Att[row][s];

    size_t cbase = (size_t)(b * LQd + q) * Dd + h * DKd + sub * 8;
    #pragma unroll
    for (int dd = 0; dd < 8; dd++) {
        float acc = 0.f;
        #pragma unroll
        for (int s = 0; s < NSd; s++) acc += att[s] * Vs[s][sub * 8 + dd];
        csh[cbase + dd] = __float2half_rn(acc);
    }
}

// ---------------- word-level attention v6: split K/V pipelining ----------------
#define HQS 72
#define W_QH 0
#define W_KV (32 * HQS)
#define W_ARR (128 * HQS)
#define W_P  (W_KV + 4 * W_ARR)
#define PROW 264
#define WSMEM_BYTES ((W_P + 32 * PROW) * 2)

__global__ __launch_bounds__(512, 2) void word_attn_h6(
    const __half* __restrict__ qwh,
    const __half* __restrict__ kwh, const __half* __restrict__ kwl,
    const __half* __restrict__ vwh, const __half* __restrict__ vwl,
    const float* __restrict__ bias_w, const float* __restrict__ attns,
    __half* __restrict__ cwh)
{
    extern __shared__ __half hsm[];
    float* Ps = (float*)(hsm + W_P);
    __half* PU = hsm + W_P;

    const int tid = threadIdx.x;
    const int wid = tid >> 5;
    const int lane = tid & 31;
    const int g = lane >> 2;
    const int t = lane & 3;
    const int wm = wid & 1;
    const int wn = wid >> 1;
    const int q0 = blockIdx.x * 32;
    const int h  = blockIdx.y;
    const int b  = blockIdx.z;

    const int q8 = lane & 7;
    const int seg = lane >> 3;
    const uint32_t smem_base = (uint32_t)__cvta_generic_to_shared(hsm);
    const uint32_t aq_off = (uint32_t)((q8 + (seg & 1) * 8) * HQS + (seg >> 1) * 8);
    const uint32_t bk_off = (uint32_t)((q8 + (seg >> 1) * 8) * HQS + (seg & 1) * 8);
    const uint32_t ap_off = (uint32_t)((q8 + (seg & 1) * 8) * PROW + (seg >> 1) * 8);
    const uint32_t v_arr  = (seg >> 1) ? (uint32_t)(W_KV + 3 * W_ARR) : (uint32_t)(W_KV + 2 * W_ARR);
    const uint32_t v_off  = (uint32_t)((q8 + (seg & 1) * 8) * HQS + wn * 8);

    {
        if (tid < 256) {
            int row = tid >> 3, ch = tid & 7;
            const __half* src = qwh + (size_t)(b * LQd + q0 + row) * Dd + h * DKd + ch * 8;
            cp_async16((uint32_t)__cvta_generic_to_shared(&hsm[W_QH + row * HQS + ch * 8]),
                       src, 16);
        }
        const size_t kvb = (size_t)(b * NSd) * NTd * Dd + h * DKd;
        const __half* srcs[4] = {kwh, kwl, vwh, vwl};
        #pragma unroll
        for (int i = 0; i < 8; i++) {
            int id = tid + 512 * i;
            int arr = id >> 10, rem = id & 1023;
            int row = rem >> 3, ch = rem & 7;
            const __half* src = srcs[arr] + kvb + (size_t)row * Dd + ch * 8;
            cp_async16((uint32_t)__cvta_generic_to_shared(
                           &hsm[W_KV + arr * W_ARR + row * HQS + ch * 8]),
                       src, 16);
        }
        cp_commit();
        cp_wait<0>();
    }
    __syncthreads();

    float om[4], oc[4];
    #pragma unroll
    for (int j = 0; j < 4; j++) { om[j] = 0.f; oc[j] = 0.f; }

    for (int s = 0; s < NSd; s++) {
        // ---- QK ----
        float pm[2][4], pc[2][4];
        #pragma unroll
        for (int nt = 0; nt < 2; nt++)
            #pragma unroll
            for (int j = 0; j < 4; j++) { pm[nt][j] = 0.f; pc[nt][j] = 0.f; }

        #pragma unroll
        for (int ks = 0; ks < 4; ks++) {
            const uint32_t kb = (uint32_t)(ks * 16);
            uint32_t ahq[4], kh4[4], kl4[4];
            uint32_t qrb = (uint32_t)(wm * 16 * HQS) + kb;
            ldsm_x4(ahq, smem_base + 2 * (W_QH + qrb + aq_off));
            uint32_t krb = (uint32_t)(wn * 16 * HQS) + kb;
            ldsm_x4(kh4, smem_base + 2 * (W_KV + krb + bk_off));
            ldsm_x4(kl4, smem_base + 2 * (W_KV + W_ARR + krb + bk_off));
            #pragma unroll
            for (int nt = 0; nt < 2; nt++) {
                mma_f16(pm[nt], ahq[0], ahq[1], ahq[2], ahq[3], kh4[2 * nt], kh4[2 * nt + 1]);
                mma_f16(pc[nt], ahq[0], ahq[1], ahq[2], ahq[3], kl4[2 * nt], kl4[2 * nt + 1]);
            }
        }
        #pragma unroll
        for (int nt = 0; nt < 2; nt++) {
            int r = wm * 16 + g;
            int c = wn * 16 + nt * 8 + 2 * t;
            *(float2*)&Ps[r * 132 + c] = make_float2(pm[nt][0] + pc[nt][0], pm[nt][1] + pc[nt][1]);
            *(float2*)&Ps[(r + 8) * 132 + c] = make_float2(pm[nt][2] + pc[nt][2], pm[nt][3] + pc[nt][3]);
        }
        __syncthreads();   // Ps visible; K[s] dead

        // issue K(s+1) — overlaps softmax + PV
        if (s + 1 < NSd) {
            const size_t kvb = (size_t)(b * NSd + s + 1) * NTd * Dd + h * DKd;
            const __half* srcs[2] = {kwh, kwl};
            #pragma unroll
            for (int i = 0; i < 4; i++) {
                int id = tid + 512 * i;
                int arr = id >> 10, rem = id & 1023;
                int row = rem >> 3, ch = rem & 7;
                const __half* src = srcs[arr] + kvb + (size_t)row * Dd + ch * 8;
                cp_async16((uint32_t)__cvta_generic_to_shared(
                               &hsm[W_KV + arr * W_ARR + row * HQS + ch * 8]),
                           src, 16);
            }
            cp_commit();
        }

        // ---- softmax ----
        const float* bb = bias_w + ((size_t)((b * NSd + s) * Hd + h) * LQd + q0) * NTd;
        #pragma unroll
        for (int rr = 0; rr < 2; rr++) {
            int r = wid * 2 + rr;
            float x0 = Ps[r * 132 + lane]       + bb[r * NTd + lane];
            float x1 = Ps[r * 132 + lane + 32]  + bb[r * NTd + lane + 32];
            float x2 = Ps[r * 132 + lane + 64]  + bb[r * NTd + lane + 64];
            float x3 = Ps[r * 132 + lane + 96]  + bb[r * NTd + lane + 96];
            float mx = fmaxf(fmaxf(x0, x1), fmaxf(x2, x3));
            #pragma unroll
            for (int o = 16; o; o >>= 1) mx = fmaxf(mx, __shfl_xor_sync(0xffffffffu, mx, o));
            x0 = __expf(x0 - mx); x1 = __expf(x1 - mx);
            x2 = __expf(x2 - mx); x3 = __expf(x3 - mx);
            float su = x0 + x1 + x2 + x3;
            #pragma unroll
            for (int o = 16; o; o >>= 1) su += __shfl_xor_sync(0xffffffffu, su, o);
            float wsc = attns[((size_t)(b * Hd + h) * LQd + q0 + r) * NSd + s] / su;
            __half h0 = __float2half_rn(x0 * wsc);
            __half h1 = __float2half_rn(x1 * wsc);
            __half h2 = __float2half_rn(x2 * wsc);
            __half h3 = __float2half_rn(x3 * wsc);
            __syncwarp();
            __half* prow = PU + r * PROW;
            prow[lane]       = h0;
            prow[lane + 32]  = h1;
            prow[lane + 64]  = h2;
            prow[lane + 96]  = h3;
        }
        if (s > 0) cp_wait<1>();
        __syncthreads();   // PU visible; V[s] visible

        // ---- PV ----
        #pragma unroll
        for (int ks = 0; ks < 8; ks++) {
            const uint32_t kb = (uint32_t)(ks * 16);
            uint32_t ph4[4], v4[4];
            uint32_t prb = (uint32_t)(wm * 16 * PROW) + kb;
            ldsm_x4(ph4, smem_base + 2 * (W_P + prb + ap_off));
            ldsm_x4_t(v4, smem_base + 2 * (v_arr + kb * HQS + v_off));
            mma_f16(om, ph4[0], ph4[1], ph4[2], ph4[3], v4[0], v4[1]);
            mma_f16(oc, ph4[0], ph4[1], ph4[2], ph4[3], v4[2], v4[3]);
        }

        if (s + 1 < NSd) {
            __syncthreads();   // V[s] dead
            const size_t kvb = (size_t)(b * NSd + s + 1) * NTd * Dd + h * DKd;
            const __half* srcs[2] = {vwh, vwl};
            #pragma unroll
            for (int i = 0; i < 4; i++) {
                int id = tid + 512 * i;
                int arr = id >> 10, rem = id & 1023;
                int row = rem >> 3, ch = rem & 7;
                const __half* src = srcs[arr] + kvb + (size_t)row * Dd + ch * 8;
                cp_async16((uint32_t)__cvta_generic_to_shared(
                               &hsm[W_KV + (2 + arr) * W_ARR + row * HQS + ch * 8]),
                           src, 16);
            }
            cp_commit();
            cp_wait<1>();
            __syncthreads();   // K(s+1) visible
        }
    }

    {
        int r = q0 + wm * 16 + g;
        int c = h * DKd + wn * 8 + 2 * t;
        float v0 = om[0] + oc[0], v1 = om[1] + oc[1];
        float v2 = om[2] + oc[2], v3 = om[3] + oc[3];
        *(__half2*)&cwh[(size_t)(b * LQd + r) * Dd + c] =
            __halves2half2(__float2half_rn(v0), __float2half_rn(v1));
        *(__half2*)&cwh[(size_t)(b * LQd + r + 8) * Dd + c] =
            __halves2half2(__float2half_rn(v2), __float2half_rn(v3));
    }
}

// ---------------- host ----------------
extern "C" void kernel_launch(void* const* d_in, const int* in_sizes, int n_in,
                              void* d_out, int out_size)
{
    const float* q      = (const float*)d_in[0];
    const float* k_s    = (const float*)d_in[1];
    const float* v_s    = (const float*)d_in[2];
    const float* k_w    = (const float*)d_in[3];
    const float* v_w    = (const float*)d_in[4];
    const float* bias_w = (const float*)d_in[5];
    const float* bias_s = (const float*)d_in[6];
    const float* gab    = (const float*)d_in[7];

    const float *wq_s, *bq_s, *wk_s, *bk_s, *wv_s, *bv_s;
    const float *wq_w, *bq_w, *wk_w, *bk_w, *wv_w, *bv_w;
    const float *fcs_w, *fcs_b, *fcw_w, *fcw_b, *fco_w, *fco_b;

    if (in_sizes[9] == 512) {
        wq_s = (const float*)d_in[8];  bq_s = (const float*)d_in[9];
        wk_s = (const float*)d_in[10]; bk_s = (const float*)d_in[11];
        wv_s = (const float*)d_in[12]; bv_s = (const float*)d_in[13];
        wq_w = (const float*)d_in[14]; bq_w = (const float*)d_in[15];
        wk_w = (const float*)d_in[16]; bk_w = (const float*)d_in[17];
        wv_w = (const float*)d_in[18]; bv_w = (const float*)d_in[19];
        fcs_w = (const float*)d_in[20]; fcs_b = (const float*)d_in[21];
        fcw_w = (const float*)d_in[22]; fcw_b = (const float*)d_in[23];
        fco_w = (const float*)d_in[24]; fco_b = (const float*)d_in[25];
    } else {
        wq_s = (const float*)d_in[8];  wk_s = (const float*)d_in[9];
        wv_s = (const float*)d_in[10]; wq_w = (const float*)d_in[11];
        wk_w = (const float*)d_in[12]; wv_w = (const float*)d_in[13];
        fcs_w = (const float*)d_in[14]; fcw_w = (const float*)d_in[15];
        bq_s = (const float*)d_in[16]; bk_s = (const float*)d_in[17];
        bv_s = (const float*)d_in[18]; bq_w = (const float*)d_in[19];
        bk_w = (const float*)d_in[20]; bv_w = (const float*)d_in[21];
        fcs_b = (const float*)d_in[22]; fcw_b = (const float*)d_in[23];
        fco_w = (const float*)d_in[24]; fco_b = (const float*)d_in[25];
    }

    float* scratch = nullptr;
    cudaGetSymbolAddress((void**)&scratch, g_scratch);
    float* s_qs  = scratch + OFF_QS;
    float* s_ks  = scratch + OFF_KS;
    float* s_vs  = scratch + OFF_VS;
    float* s_att = scratch + OFF_ATT;
    __half* hb = (__half*)(scratch + OFF_HALF);
    __half* acth = hb + H_ACTH;
    __half* wth  = hb + H_WTH;
    __half* wtl  = hb + H_WTL;
    __half* qwh  = hb + H_QWH;
    __half* kwh  = hb + H_KWH;
    __half* kwl  = hb + H_KWL;
    __half* vwh  = hb + H_VWH;
    __half* vwl  = hb + H_VWL;
    __half* csh  = hb + H_CSH;
    __half* cwh  = hb + H_CWH;
    __half* cath = hb + H_CATH;

    cudaFuncSetAttribute(gemm_cfg, cudaFuncAttributeMaxDynamicSharedMemorySize, HSMEM_BYTES);
    cudaFuncSetAttribute(word_attn_h6, cudaFuncAttributeMaxDynamicSharedMemorySize, WSMEM_BYTES);

    // prep
    ASplitArgs aa;
    aa.src[0] = q; aa.src[1] = k_s; aa.src[2] = v_s; aa.src[3] = k_w; aa.src[4] = v_w;
    act_split<<<dim3(256, 5), 256>>>(aa, acth);
    WSplitArgs wa;
    wa.src[0] = wq_s; wa.src[1] = wk_s; wa.src[2] = wv_s;
    wa.src[3] = wq_w; wa.src[4] = wk_w; wa.src[5] = wv_w;
    wa.src[6] = fcs_w; wa.src[7] = fcw_w; wa.src[8] = fco_w;
    w_transplit<<<dim3(16, 32, 9), dim3(32, 8)>>>(wa, wth, wtl);

    // all projections in ONE launch
    {
        GemmCfg c = {};
        c.K = 512; c.ldc = 512;
        c.Ah[0] = acth + AKW; c.Bh[0] = wth + WOFF(4); c.Bl[0] = wtl + WOFF(4);
        c.Ah[1] = acth + AVW; c.Bh[1] = wth + WOFF(5); c.Bl[1] = wtl + WOFF(5);
        c.Ah[2] = acth + AQ;  c.Bh[2] = wth + WOFF(0); c.Bl[2] = wtl + WOFF(0);
        c.Ah[3] = acth + AQ;  c.Bh[3] = wth + WOFF(3); c.Bl[3] = wtl + WOFF(3);
        c.Ah[4] = acth + AKS; c.Bh[4] = wth + WOFF(1); c.Bl[4] = wtl + WOFF(1);
        c.Ah[5] = acth + AVS; c.Bh[5] = wth + WOFF(2); c.Bl[5] = wtl + WOFF(2);
        c.bias[0] = bk_w; c.bias[1] = bv_w; c.bias[2] = bq_s;
        c.bias[3] = bq_w; c.bias[4] = bk_s; c.bias[5] = bv_s;
        c.bscale[0] = 1.f; c.bscale[1] = 1.f; c.bscale[2] = 1.f;
        c.bscale[3] = 0.125f; c.bscale[4] = 1.f; c.bscale[5] = 1.f;
        c.M[0] = 12288; c.M[1] = 12288; c.M[2] = 1024;
        c.M[3] = 1024;  c.M[4] = 96;    c.M[5] = 96;
        c.mode[0] = 1; c.mode[1] = 1; c.mode[2] = 0;
        c.mode[3] = 2; c.mode[4] = 0; c.mode[5] = 0;
        c.Ch[0] = kwh; c.Cl[0] = kwl;
        c.Ch[1] = vwh; c.Cl[1] = vwl;
        c.Cf[2] = s_qs;
        c.Ch[3] = qwh;
        c.Cf[4] = s_ks;
        c.Cf[5] = s_vs;
        gemm_cfg<<<dim3(8, 96, 6), 256, HSMEM_BYTES>>>(c);
    }

    sent_attn8<<<dim3(Hd, BB, 8), 256>>>(s_qs, s_ks, s_vs, bias_s, gab, s_att, csh);

    word_attn_h6<<<dim3(8, Hd, BB), 512, WSMEM_BYTES>>>(
        qwh, kwh, kwl, vwh, vwl, bias_w, s_att, cwh);

    // fcs / fcw -> fp16 cat (hi only; fco reads only cath)
    {
        GemmCfg c = {};
        c.K = 512; c.ldc = 1024;
        c.Ah[0] = csh; c.Bh[0] = wth + WOFF(6); c.Bl[0] = wtl + WOFF(6);
        c.Ah[1] = cwh; c.Bh[1] = wth + WOFF(7); c.Bl[1] = wtl + WOFF(7);
        c.bias[0] = fcs_b; c.bias[1] = fcw_b;
        c.bscale[0] = 1.f; c.bscale[1] = 1.f;
        c.M[0] = 1024; c.M[1] = 1024;
        c.mode[0] = 2; c.mode[1] = 2;
        c.Ch[0] = cath;
        c.Ch[1] = cath + 512;
        gemm_cfg<<<dim3(8, 8, 2), 256, HSMEM_BYTES>>>(c);
    }
    // final fco -> fp32 out
    {
        GemmCfg c = {};
        c.K = 1024; c.ldc = 512;
        c.Ah[0] = cath; c.Bh[0] = wth + WOFF(8); c.Bl[0] = wtl + WOFF(8);
        c.bias[0] = fco_b;
        c.bscale[0] = 1.f;
        c.M[0] = 1024;
        c.mode[0] = 0;
        c.Cf[0] = (float*)d_out;
        gemm_cfg<<<dim3(8, 8, 1), 256, HSMEM_BYTES>>>(c);
    }
}

// round 17
// speedup vs baseline: 1.0461x; 1.0135x over previous
#include <cuda_runtime.h>
#include <cuda_fp16.h>
#include <math.h>
#include <stdint.h>

// Problem constants
#define BB   4
#define LQd  256
#define NSd  24
#define NTd  128
#define Dd   512
#define Hd   8
#define DKd  64

// ---------------- scratch layout ----------------
#define OFF_QS   0
#define OFF_KS   524288
#define OFF_VS   573440
#define OFF_ATT  622592
#define OFF_HALF 819200
#define H_ACTH 0
#define H_ACTL 13205504
#define H_WTH  26411008
#define H_WTL  29032448
#define H_QWH  31653888
#define H_QWL  32178176
#define H_KWH  32702464
#define H_KWL  38993920
#define H_VWH  45285376
#define H_VWL  51576832
#define H_CSH  57868288
#define H_CSL  58392576
#define H_CWH  58916864
#define H_CWL  59441152
#define H_CATH 59965440
#define H_CATL 61014016
#define H_TOTAL 62062592
#define SCRATCH_TOTAL (OFF_HALF + H_TOTAL / 2)
__device__ float g_scratch[SCRATCH_TOTAL];

#define AQ   0
#define AKS  524288
#define AVS  573440
#define AKW  622592
#define AVW  6914048
#define WOFF(i) ((i) * 262144)

// ---------------- helpers ----------------
__device__ __forceinline__ void split_h(float x, __half& hi, __half& lo) {
    hi = __float2half_rn(x);
    lo = __float2half_rn(x - __half2float(hi));
}
__device__ __forceinline__ void mma_f16(float d[4],
                                        uint32_t a0, uint32_t a1, uint32_t a2, uint32_t a3,
                                        uint32_t b0, uint32_t b1) {
    asm volatile(
        "mma.sync.aligned.m16n8k16.row.col.f32.f16.f16.f32 "
        "{%0,%1,%2,%3},{%4,%5,%6,%7},{%8,%9},{%0,%1,%2,%3};"
        : "+f"(d[0]), "+f"(d[1]), "+f"(d[2]), "+f"(d[3])
        : "r"(a0), "r"(a1), "r"(a2), "r"(a3), "r"(b0), "r"(b1));
}
__device__ __forceinline__ void ldsm_x4(uint32_t r[4], uint32_t addr) {
    asm volatile("ldmatrix.sync.aligned.m8n8.x4.shared.b16 {%0,%1,%2,%3}, [%4];"
                 : "=r"(r[0]), "=r"(r[1]), "=r"(r[2]), "=r"(r[3]) : "r"(addr));
}
__device__ __forceinline__ void ldsm_x4_t(uint32_t r[4], uint32_t addr) {
    asm volatile("ldmatrix.sync.aligned.m8n8.x4.trans.shared.b16 {%0,%1,%2,%3}, [%4];"
                 : "=r"(r[0]), "=r"(r[1]), "=r"(r[2]), "=r"(r[3]) : "r"(addr));
}
__device__ __forceinline__ void cp_async16(uint32_t smem_addr, const void* gptr, int src_bytes) {
    asm volatile("cp.async.cg.shared.global [%0], [%1], 16, %2;"
                 :: "r"(smem_addr), "l"(gptr), "r"(src_bytes) : "memory");
}
__device__ __forceinline__ void cp_commit() { asm volatile("cp.async.commit_group;" ::: "memory"); }
template <int N>
__device__ __forceinline__ void cp_wait() { asm volatile("cp.async.wait_group %0;" :: "n"(N) : "memory"); }

// ---------------- prep: convert activations to fp16 ----------------
struct ASplitArgs { const float* src[5]; };
__constant__ int c_alen[5] = {524288, 49152, 49152, 6291456, 6291456};
__constant__ int c_aoff[5] = {AQ, AKS, AVS, AKW, AVW};

__global__ __launch_bounds__(256) void act_split(ASplitArgs args, __half* acth)
{
    int z = blockIdx.y;
    int n = c_alen[z];
    const float* s = args.src[z];
    __half* dh = acth + c_aoff[z];
    for (int i = blockIdx.x * 256 + threadIdx.x; i < n; i += gridDim.x * 256) {
        dh[i] = __float2half_rn(s[i]);
    }
}

// ---------------- prep: transpose+split weights ----------------
struct WSplitArgs { const float* src[9]; };
__constant__ int c_wK[9] = {512, 512, 512, 512, 512, 512, 512, 512, 1024};
__constant__ int c_woff[9] = {WOFF(0), WOFF(1), WOFF(2), WOFF(3), WOFF(4),
                              WOFF(5), WOFF(6), WOFF(7), WOFF(8)};
__constant__ float c_wscale[9] = {1.f, 1.f, 1.f, 0.125f, 1.f, 1.f, 1.f, 1.f, 1.f};

__global__ void w_transplit(WSplitArgs args, __half* wth, __half* wtl)
{
    int z = blockIdx.z;
    int Kw = c_wK[z];
    int k0 = blockIdx.y * 32;
    if (k0 >= Kw) return;
    int n0 = blockIdx.x * 32;
    const float* W = args.src[z];
    float sc = c_wscale[z];
    __half* th = wth + c_woff[z];
    __half* tl = wtl + c_woff[z];

    __shared__ float ts[32][33];
    int tx = threadIdx.x, ty = threadIdx.y;
    #pragma unroll
    for (int r = 0; r < 4; r++)
        ts[ty + 8 * r][tx] = W[(size_t)(k0 + ty + 8 * r) * 512 + n0 + tx];
    __syncthreads();
    #pragma unroll
    for (int r = 0; r < 4; r++) {
        int n = n0 + ty + 8 * r;
        int k = k0 + tx;
        __half hi, lo;
        split_h(sc * ts[tx][ty + 8 * r], hi, lo);
        th[(size_t)n * Kw + k] = hi;
        tl[(size_t)n * Kw + k] = lo;
    }
}

// ---------------- 2-term GEMM: A fp16, B split hi/lo, BK=64, 3-stage pipeline ----------------
// mode: 0 = fp32 out, 1 = split fp16 hi+lo out, 2 = fp16 hi only
#define GHS 72                                  // 64 halves + 8 pad per row
#define G_A 128
#define G_B 64
#define HSTAGE ((G_A + 2 * G_B) * GHS)          // 18432 halves = 36864 B
#define HSMEM_BYTES (3 * HSTAGE * 2)            // 110592 B -> 2 CTAs/SM

struct GemmCfg {
    const __half* Ah[6];
    const __half* Bh[6]; const __half* Bl[6];
    const float* bias[6];
    float* Cf[6];
    __half* Ch[6]; __half* Cl[6];
    int M[6]; int mode[6]; float bscale[6];
    int K; int ldc;
};

__global__ __launch_bounds__(256, 2) void gemm_cfg(GemmCfg cfg)
{
    extern __shared__ __half hsm[];

    const int z = blockIdx.z;
    const int M = cfg.M[z];
    const int row0 = blockIdx.y * 128;
    if (row0 >= M) return;

    const __half* Ah_g = cfg.Ah[z];
    const __half* Bh_g = cfg.Bh[z];
    const __half* Bl_g = cfg.Bl[z];
    const float* bias  = cfg.bias[z];
    const int mode     = cfg.mode[z];
    const float bsc    = cfg.bscale[z];
    const int K        = cfg.K;
    const int ldc      = cfg.ldc;

    const int tid = threadIdx.x;
    const int wid = tid >> 5;
    const int lane = tid & 31;
    const int g = lane >> 2;
    const int t = lane & 3;
    const int wm = wid & 3;
    const int wn = wid >> 2;
    const int col0 = blockIdx.x * 64;

    const int q8 = lane & 7;
    const int seg = lane >> 3;
    const uint32_t smem_base = (uint32_t)__cvta_generic_to_shared(hsm);
    const uint32_t a_off = (uint32_t)((q8 + (seg & 1) * 8) * GHS + (seg >> 1) * 8);
    const uint32_t b_off = (uint32_t)((q8 + (seg >> 1) * 8) * GHS + (seg & 1) * 8);

    float dm[2][4][4], dc[2][4][4];
    #pragma unroll
    for (int mt = 0; mt < 2; mt++)
        #pragma unroll
        for (int nt = 0; nt < 4; nt++)
            #pragma unroll
            for (int j = 0; j < 4; j++) { dm[mt][nt][j] = 0.f; dc[mt][nt][j] = 0.f; }

    const int ktiles = K >> 6;

    // prologue: fill stages 0 and 1
    #pragma unroll
    for (int p = 0; p < 2; p++) {
        __half* Ahs = hsm + p * HSTAGE;
        __half* Bhs = Ahs + G_A * GHS;
        __half* Bls = Bhs + G_B * GHS;
        int k0 = p << 6;
        #pragma unroll
        for (int i = 0; i < 4; i++) {       // A: 128 rows x 8 chunks = 1024 slots
            int id = tid + 256 * i;
            int row = id >> 3, ch = id & 7;
            int r = row0 + row;
            int rc = r < M ? r : (M - 1);
            int pb = r < M ? 16 : 0;
            cp_async16((uint32_t)__cvta_generic_to_shared(&Ahs[row * GHS + ch * 8]),
                       &Ah_g[(size_t)rc * K + k0 + ch * 8], pb);
        }
        #pragma unroll
        for (int i = 0; i < 4; i++) {       // B: 2 arrays x 64 rows x 8 chunks = 1024 slots
            int id = tid + 256 * i;
            int arr = id >> 9, rem = id & 511;
            int row = rem >> 3, ch = rem & 7;
            const __half* src = (arr ? Bl_g : Bh_g) + (size_t)(col0 + row) * K + k0 + ch * 8;
            __half* dst = (arr ? Bls : Bhs) + row * GHS + ch * 8;
            cp_async16((uint32_t)__cvta_generic_to_shared(dst), src, 16);
        }
        cp_commit();
    }
    cp_wait<1>();
    __syncthreads();

    int cst = 0;

    for (int kt = 0; kt < ktiles; kt++) {
        const uint32_t stage = smem_base + (uint32_t)((cst * HSTAGE) * 2);

        #pragma unroll
        for (int ks = 0; ks < 4; ks++) {
            const uint32_t kb = (uint32_t)(ks * 16);
            uint32_t ah[2][4];
            #pragma unroll
            for (int mt = 0; mt < 2; mt++) {
                uint32_t rbase = (uint32_t)((wm * 32 + mt * 16) * GHS) + kb;
                ldsm_x4(ah[mt], stage + 2 * (rbase + a_off));
            }
            uint32_t bh[4][2], bl[4][2];
            #pragma unroll
            for (int p = 0; p < 2; p++) {
                uint32_t nbase = (uint32_t)((wn * 32 + p * 16) * GHS) + kb;
                uint32_t r4[4];
                ldsm_x4(r4, stage + 2 * (G_A * GHS + nbase + b_off));
                bh[2 * p][0] = r4[0]; bh[2 * p][1] = r4[1];
                bh[2 * p + 1][0] = r4[2]; bh[2 * p + 1][1] = r4[3];
                ldsm_x4(r4, stage + 2 * (G_A * GHS + G_B * GHS + nbase + b_off));
                bl[2 * p][0] = r4[0]; bl[2 * p][1] = r4[1];
                bl[2 * p + 1][0] = r4[2]; bl[2 * p + 1][1] = r4[3];
            }
            #pragma unroll
            for (int nt = 0; nt < 4; nt++) {
                #pragma unroll
                for (int mt = 0; mt < 2; mt++) {
                    mma_f16(dm[mt][nt], ah[mt][0], ah[mt][1], ah[mt][2], ah[mt][3], bh[nt][0], bh[nt][1]);
                    mma_f16(dc[mt][nt], ah[mt][0], ah[mt][1], ah[mt][2], ah[mt][3], bl[nt][0], bl[nt][1]);
                }
            }
        }

        int nk = kt + 2;
        if (nk < ktiles) {
            int st = nk % 3;
            __half* Ahs = hsm + st * HSTAGE;
            __half* Bhs = Ahs + G_A * GHS;
            __half* Bls = Bhs + G_B * GHS;
            int k0 = nk << 6;
            #pragma unroll
            for (int i = 0; i < 4; i++) {
                int id = tid + 256 * i;
                int row = id >> 3, ch = id & 7;
                int r = row0 + row;
                int rc = r < M ? r : (M - 1);
                int pb = r < M ? 16 : 0;
                cp_async16((uint32_t)__cvta_generic_to_shared(&Ahs[row * GHS + ch * 8]),
                           &Ah_g[(size_t)rc * K + k0 + ch * 8], pb);
            }
            #pragma unroll
            for (int i = 0; i < 4; i++) {
                int id = tid + 256 * i;
                int arr = id >> 9, rem = id & 511;
                int row = rem >> 3, ch = rem & 7;
                const __half* src = (arr ? Bl_g : Bh_g) + (size_t)(col0 + row) * K + k0 + ch * 8;
                __half* dst = (arr ? Bls : Bhs) + row * GHS + ch * 8;
                cp_async16((uint32_t)__cvta_generic_to_shared(dst), src, 16);
            }
        }
        cp_commit();
        cp_wait<1>();
        __syncthreads();

        cst = (cst == 2) ? 0 : cst + 1;
    }

    #pragma unroll
    for (int mt = 0; mt < 2; mt++) {
        #pragma unroll
        for (int nt = 0; nt < 4; nt++) {
            int r = row0 + wm * 32 + mt * 16 + g;
            int c = col0 + wn * 32 + nt * 8 + 2 * t;
            float2 bz = *(const float2*)&bias[c];
            float o0 = dm[mt][nt][0] + dc[mt][nt][0] + bsc * bz.x;
            float o1 = dm[mt][nt][1] + dc[mt][nt][1] + bsc * bz.y;
            float o2 = dm[mt][nt][2] + dc[mt][nt][2] + bsc * bz.x;
            float o3 = dm[mt][nt][3] + dc[mt][nt][3] + bsc * bz.y;
            if (mode == 0) {
                float* Cf = cfg.Cf[z];
                if (r < M)     *(float2*)&Cf[(size_t)r * ldc + c] = make_float2(o0, o1);
                if (r + 8 < M) *(float2*)&Cf[(size_t)(r + 8) * ldc + c] = make_float2(o2, o3);
            } else if (mode == 1) {
                __half* Ch = cfg.Ch[z];
                __half* Cl = cfg.Cl[z];
                __half h0, l0, h1, l1;
                if (r < M) {
                    split_h(o0, h0, l0); split_h(o1, h1, l1);
                    *(__half2*)&Ch[(size_t)r * ldc + c] = __halves2half2(h0, h1);
                    *(__half2*)&Cl[(size_t)r * ldc + c] = __halves2half2(l0, l1);
                }
                if (r + 8 < M) {
                    split_h(o2, h0, l0); split_h(o3, h1, l1);
                    *(__half2*)&Ch[(size_t)(r + 8) * ldc + c] = __halves2half2(h0, h1);
                    *(__half2*)&Cl[(size_t)(r + 8) * ldc + c] = __halves2half2(l0, l1);
                }
            } else {
                __half* Ch = cfg.Ch[z];
                if (r < M)
                    *(__half2*)&Ch[(size_t)r * ldc + c] =
                        __halves2half2(__float2half_rn(o0), __float2half_rn(o1));
                if (r + 8 < M)
                    *(__half2*)&Ch[(size_t)(r + 8) * ldc + c] =
                        __halves2half2(__float2half_rn(o2), __float2half_rn(o3));
            }
        }
    }
}

// ---------------- sentence-level graph attention (8 threads/row) ----------------
__global__ __launch_bounds__(256) void sent_attn8(
    const float* __restrict__ qs, const float* __restrict__ ksn,
    const float* __restrict__ vsn, const float* __restrict__ bias_s,
    const float* __restrict__ gab,
    float* __restrict__ attns_out,
    __half* __restrict__ csh)
{
    const int h = blockIdx.x, b = blockIdx.y;
    const int q0 = blockIdx.z * 32;
    const int tid = threadIdx.x;
    const int row = tid >> 3;
    const int sub = tid & 7;
    const int q = q0 + row;

    __shared__ float Ks[NSd][DKd + 1];
    __shared__ float Vs[NSd][DKd + 1];
    __shared__ float G[NSd][NSd + 1];
    __shared__ float Att[32][NSd + 1];

    for (int idx = tid; idx < NSd * DKd; idx += 256) {
        int s = idx >> 6, k = idx & 63;
        Ks[s][k] = ksn[(size_t)(b * NSd + s) * Dd + h * DKd + k];
        Vs[s][k] = vsn[(size_t)(b * NSd + s) * Dd + h * DKd + k];
    }
    for (int idx = tid; idx < NSd * NSd; idx += 256) {
        int s = idx / NSd, tt = idx % NSd;
        G[s][tt] = gab[((size_t)(b * Hd + h) * NSd + s) * NSd + tt];
    }
    __syncthreads();

    float qreg[8];
    const float* qrow = qs + (size_t)(b * LQd + q) * Dd + h * DKd + sub * 8;
    #pragma unroll
    for (int k = 0; k < 8; k++) qreg[k] = qrow[k] * 0.125f;

    float a[NSd];
    #pragma unroll
    for (int s = 0; s < NSd; s++) {
        float dd = 0.f;
        #pragma unroll
        for (int k = 0; k < 8; k++) dd += qreg[k] * Ks[s][sub * 8 + k];
        a[s] = dd;
    }
    #pragma unroll
    for (int s = 0; s < NSd; s++) {
        a[s] += __shfl_xor_sync(0xffffffffu, a[s], 1);
        a[s] += __shfl_xor_sync(0xffffffffu, a[s], 2);
        a[s] += __shfl_xor_sync(0xffffffffu, a[s], 4);
    }
    const float* bsrow = bias_s + ((size_t)(b * Hd + h) * LQd + q) * NSd;
    #pragma unroll
    for (int s = 0; s < NSd; s++) a[s] += bsrow[s];

    float m = -1e30f;
    #pragma unroll
    for (int s = 0; s < NSd; s++) m = fmaxf(m, a[s]);
    float smx[NSd]; float sum = 0.f;
    #pragma unroll
    for (int s = 0; s < NSd; s++) { smx[s] = __expf(a[s] - m); sum += smx[s]; }
    float inv = 1.f / sum;

    const int t0 = sub * 3;
    float an[3];
    #pragma unroll
    for (int j = 0; j < 3; j++) {
        float dd = 0.f;
        #pragma unroll
        for (int s = 0; s < NSd; s++) dd += smx[s] * G[s][t0 + j];
        float gg = dd * inv;
        an[j] = a[t0 + j] - 0.5f * gg * gg;
    }

    float m2 = -1e30f;
    #pragma unroll
    for (int j = 0; j < 3; j++) m2 = fmaxf(m2, an[j]);
    m2 = fmaxf(m2, __shfl_xor_sync(0xffffffffu, m2, 1));
    m2 = fmaxf(m2, __shfl_xor_sync(0xffffffffu, m2, 2));
    m2 = fmaxf(m2, __shfl_xor_sync(0xffffffffu, m2, 4));
    float e[3]; float su = 0.f;
    #pragma unroll
    for (int j = 0; j < 3; j++) { e[j] = __expf(an[j] - m2); su += e[j]; }
    su += __shfl_xor_sync(0xffffffffu, su, 1);
    su += __shfl_xor_sync(0xffffffffu, su, 2);
    su += __shfl_xor_sync(0xffffffffu, su, 4);
    float inv2 = 1.f / su;

    float* arow = attns_out + ((size_t)(b * Hd + h) * LQd + q) * NSd;
    #pragma unroll
    for (int j = 0; j < 3; j++) {
        float v = e[j] * inv2;
        Att[row][t0 + j] = v;
        arow[t0 + j] = v;
    }
    __syncwarp();

    float att[NSd];
    #pragma unroll
    for (int s = 0; s < NSd; s++) att[s] = Att[row][s];

    size_t cbase = (size_t)(b * LQd + q) * Dd + h * DKd + sub * 8;
    #pragma unroll
    for (int dd = 0; dd < 8; dd++) {
        float acc = 0.f;
        #pragma unroll
        for (int s = 0; s < NSd; s++) acc += att[s] * Vs[s][sub * 8 + dd];
        csh[cbase + dd] = __float2half_rn(acc);
    }
}

// ---------------- word-level attention v6: split K/V pipelining ----------------
#define HQS 72
#define W_QH 0
#define W_KV (32 * HQS)
#define W_ARR (128 * HQS)
#define W_P  (W_KV + 4 * W_ARR)
#define PROW 264
#define WSMEM_BYTES ((W_P + 32 * PROW) * 2)

__global__ __launch_bounds__(512, 2) void word_attn_h6(
    const __half* __restrict__ qwh,
    const __half* __restrict__ kwh, const __half* __restrict__ kwl,
    const __half* __restrict__ vwh, const __half* __restrict__ vwl,
    const float* __restrict__ bias_w, const float* __restrict__ attns,
    __half* __restrict__ cwh)
{
    extern __shared__ __half hsm[];
    float* Ps = (float*)(hsm + W_P);
    __half* PU = hsm + W_P;

    const int tid = threadIdx.x;
    const int wid = tid >> 5;
    const int lane = tid & 31;
    const int g = lane >> 2;
    const int t = lane & 3;
    const int wm = wid & 1;
    const int wn = wid >> 1;
    const int q0 = blockIdx.x * 32;
    const int h  = blockIdx.y;
    const int b  = blockIdx.z;

    const int q8 = lane & 7;
    const int seg = lane >> 3;
    const uint32_t smem_base = (uint32_t)__cvta_generic_to_shared(hsm);
    const uint32_t aq_off = (uint32_t)((q8 + (seg & 1) * 8) * HQS + (seg >> 1) * 8);
    const uint32_t bk_off = (uint32_t)((q8 + (seg >> 1) * 8) * HQS + (seg & 1) * 8);
    const uint32_t ap_off = (uint32_t)((q8 + (seg & 1) * 8) * PROW + (seg >> 1) * 8);
    const uint32_t v_arr  = (seg >> 1) ? (uint32_t)(W_KV + 3 * W_ARR) : (uint32_t)(W_KV + 2 * W_ARR);
    const uint32_t v_off  = (uint32_t)((q8 + (seg & 1) * 8) * HQS + wn * 8);

    {
        if (tid < 256) {
            int row = tid >> 3, ch = tid & 7;
            const __half* src = qwh + (size_t)(b * LQd + q0 + row) * Dd + h * DKd + ch * 8;
            cp_async16((uint32_t)__cvta_generic_to_shared(&hsm[W_QH + row * HQS + ch * 8]),
                       src, 16);
        }
        const size_t kvb = (size_t)(b * NSd) * NTd * Dd + h * DKd;
        const __half* srcs[4] = {kwh, kwl, vwh, vwl};
        #pragma unroll
        for (int i = 0; i < 8; i++) {
            int id = tid + 512 * i;
            int arr = id >> 10, rem = id & 1023;
            int row = rem >> 3, ch = rem & 7;
            const __half* src = srcs[arr] + kvb + (size_t)row * Dd + ch * 8;
            cp_async16((uint32_t)__cvta_generic_to_shared(
                           &hsm[W_KV + arr * W_ARR + row * HQS + ch * 8]),
                       src, 16);
        }
        cp_commit();
        cp_wait<0>();
    }
    __syncthreads();

    float om[4], oc[4];
    #pragma unroll
    for (int j = 0; j < 4; j++) { om[j] = 0.f; oc[j] = 0.f; }

    for (int s = 0; s < NSd; s++) {
        // ---- QK ----
        float pm[2][4], pc[2][4];
        #pragma unroll
        for (int nt = 0; nt < 2; nt++)
            #pragma unroll
            for (int j = 0; j < 4; j++) { pm[nt][j] = 0.f; pc[nt][j] = 0.f; }

        #pragma unroll
        for (int ks = 0; ks < 4; ks++) {
            const uint32_t kb = (uint32_t)(ks * 16);
            uint32_t ahq[4], kh4[4], kl4[4];
            uint32_t qrb = (uint32_t)(wm * 16 * HQS) + kb;
            ldsm_x4(ahq, smem_base + 2 * (W_QH + qrb + aq_off));
            uint32_t krb = (uint32_t)(wn * 16 * HQS) + kb;
            ldsm_x4(kh4, smem_base + 2 * (W_KV + krb + bk_off));
            ldsm_x4(kl4, smem_base + 2 * (W_KV + W_ARR + krb + bk_off));
            #pragma unroll
            for (int nt = 0; nt < 2; nt++) {
                mma_f16(pm[nt], ahq[0], ahq[1], ahq[2], ahq[3], kh4[2 * nt], kh4[2 * nt + 1]);
                mma_f16(pc[nt], ahq[0], ahq[1], ahq[2], ahq[3], kl4[2 * nt], kl4[2 * nt + 1]);
            }
        }
        #pragma unroll
        for (int nt = 0; nt < 2; nt++) {
            int r = wm * 16 + g;
            int c = wn * 16 + nt * 8 + 2 * t;
            *(float2*)&Ps[r * 132 + c] = make_float2(pm[nt][0] + pc[nt][0], pm[nt][1] + pc[nt][1]);
            *(float2*)&Ps[(r + 8) * 132 + c] = make_float2(pm[nt][2] + pc[nt][2], pm[nt][3] + pc[nt][3]);
        }
        __syncthreads();   // Ps visible; K[s] dead

        // issue K(s+1) — overlaps softmax + PV
        if (s + 1 < NSd) {
            const size_t kvb = (size_t)(b * NSd + s + 1) * NTd * Dd + h * DKd;
            const __half* srcs[2] = {kwh, kwl};
            #pragma unroll
            for (int i = 0; i < 4; i++) {
                int id = tid + 512 * i;
                int arr = id >> 10, rem = id & 1023;
                int row = rem >> 3, ch = rem & 7;
                const __half* src = srcs[arr] + kvb + (size_t)row * Dd + ch * 8;
                cp_async16((uint32_t)__cvta_generic_to_shared(
                               &hsm[W_KV + arr * W_ARR + row * HQS + ch * 8]),
                           src, 16);
            }
            cp_commit();
        }

        // ---- softmax ----
        const float* bb = bias_w + ((size_t)((b * NSd + s) * Hd + h) * LQd + q0) * NTd;
        #pragma unroll
        for (int rr = 0; rr < 2; rr++) {
            int r = wid * 2 + rr;
            float x0 = Ps[r * 132 + lane]       + bb[r * NTd + lane];
            float x1 = Ps[r * 132 + lane + 32]  + bb[r * NTd + lane + 32];
            float x2 = Ps[r * 132 + lane + 64]  + bb[r * NTd + lane + 64];
            float x3 = Ps[r * 132 + lane + 96]  + bb[r * NTd + lane + 96];
            float mx = fmaxf(fmaxf(x0, x1), fmaxf(x2, x3));
            #pragma unroll
            for (int o = 16; o; o >>= 1) mx = fmaxf(mx, __shfl_xor_sync(0xffffffffu, mx, o));
            x0 = __expf(x0 - mx); x1 = __expf(x1 - mx);
            x2 = __expf(x2 - mx); x3 = __expf(x3 - mx);
            float su = x0 + x1 + x2 + x3;
            #pragma unroll
            for (int o = 16; o; o >>= 1) su += __shfl_xor_sync(0xffffffffu, su, o);
            float wsc = attns[((size_t)(b * Hd + h) * LQd + q0 + r) * NSd + s] / su;
            __half h0 = __float2half_rn(x0 * wsc);
            __half h1 = __float2half_rn(x1 * wsc);
            __half h2 = __float2half_rn(x2 * wsc);
            __half h3 = __float2half_rn(x3 * wsc);
            __syncwarp();
            __half* prow = PU + r * PROW;
            prow[lane]       = h0;
            prow[lane + 32]  = h1;
            prow[lane + 64]  = h2;
            prow[lane + 96]  = h3;
        }
        if (s > 0) cp_wait<1>();
        __syncthreads();   // PU visible; V[s] visible

        // ---- PV ----
        #pragma unroll
        for (int ks = 0; ks < 8; ks++) {
            const uint32_t kb = (uint32_t)(ks * 16);
            uint32_t ph4[4], v4[4];
            uint32_t prb = (uint32_t)(wm * 16 * PROW) + kb;
            ldsm_x4(ph4, smem_base + 2 * (W_P + prb + ap_off));
            ldsm_x4_t(v4, smem_base + 2 * (v_arr + kb * HQS + v_off));
            mma_f16(om, ph4[0], ph4[1], ph4[2], ph4[3], v4[0], v4[1]);
            mma_f16(oc, ph4[0], ph4[1], ph4[2], ph4[3], v4[2], v4[3]);
        }

        if (s + 1 < NSd) {
            __syncthreads();   // V[s] dead
            const size_t kvb = (size_t)(b * NSd + s + 1) * NTd * Dd + h * DKd;
            const __half* srcs[2] = {vwh, vwl};
            #pragma unroll
            for (int i = 0; i < 4; i++) {
                int id = tid + 512 * i;
                int arr = id >> 10, rem = id & 1023;
                int row = rem >> 3, ch = rem & 7;
                const __half* src = srcs[arr] + kvb + (size_t)row * Dd + ch * 8;
                cp_async16((uint32_t)__cvta_generic_to_shared(
                               &hsm[W_KV + (2 + arr) * W_ARR + row * HQS + ch * 8]),
                           src, 16);
            }
            cp_commit();
            cp_wait<1>();
            __syncthreads();   // K(s+1) visible
        }
    }

    {
        int r = q0 + wm * 16 + g;
        int c = h * DKd + wn * 8 + 2 * t;
        float v0 = om[0] + oc[0], v1 = om[1] + oc[1];
        float v2 = om[2] + oc[2], v3 = om[3] + oc[3];
        *(__half2*)&cwh[(size_t)(b * LQd + r) * Dd + c] =
            __halves2half2(__float2half_rn(v0), __float2half_rn(v1));
        *(__half2*)&cwh[(size_t)(b * LQd + r + 8) * Dd + c] =
            __halves2half2(__float2half_rn(v2), __float2half_rn(v3));
    }
}

// ---------------- host ----------------
extern "C" void kernel_launch(void* const* d_in, const int* in_sizes, int n_in,
                              void* d_out, int out_size)
{
    const float* q      = (const float*)d_in[0];
    const float* k_s    = (const float*)d_in[1];
    const float* v_s    = (const float*)d_in[2];
    const float* k_w    = (const float*)d_in[3];
    const float* v_w    = (const float*)d_in[4];
    const float* bias_w = (const float*)d_in[5];
    const float* bias_s = (const float*)d_in[6];
    const float* gab    = (const float*)d_in[7];

    const float *wq_s, *bq_s, *wk_s, *bk_s, *wv_s, *bv_s;
    const float *wq_w, *bq_w, *wk_w, *bk_w, *wv_w, *bv_w;
    const float *fcs_w, *fcs_b, *fcw_w, *fcw_b, *fco_w, *fco_b;

    if (in_sizes[9] == 512) {
        wq_s = (const float*)d_in[8];  bq_s = (const float*)d_in[9];
        wk_s = (const float*)d_in[10]; bk_s = (const float*)d_in[11];
        wv_s = (const float*)d_in[12]; bv_s = (const float*)d_in[13];
        wq_w = (const float*)d_in[14]; bq_w = (const float*)d_in[15];
        wk_w = (const float*)d_in[16]; bk_w = (const float*)d_in[17];
        wv_w = (const float*)d_in[18]; bv_w = (const float*)d_in[19];
        fcs_w = (const float*)d_in[20]; fcs_b = (const float*)d_in[21];
        fcw_w = (const float*)d_in[22]; fcw_b = (const float*)d_in[23];
        fco_w = (const float*)d_in[24]; fco_b = (const float*)d_in[25];
    } else {
        wq_s = (const float*)d_in[8];  wk_s = (const float*)d_in[9];
        wv_s = (const float*)d_in[10]; wq_w = (const float*)d_in[11];
        wk_w = (const float*)d_in[12]; wv_w = (const float*)d_in[13];
        fcs_w = (const float*)d_in[14]; fcw_w = (const float*)d_in[15];
        bq_s = (const float*)d_in[16]; bk_s = (const float*)d_in[17];
        bv_s = (const float*)d_in[18]; bq_w = (const float*)d_in[19];
        bk_w = (const float*)d_in[20]; bv_w = (const float*)d_in[21];
        fcs_b = (const float*)d_in[22]; fcw_b = (const float*)d_in[23];
        fco_w = (const float*)d_in[24]; fco_b = (const float*)d_in[25];
    }

    float* scratch = nullptr;
    cudaGetSymbolAddress((void**)&scratch, g_scratch);
    float* s_qs  = scratch + OFF_QS;
    float* s_ks  = scratch + OFF_KS;
    float* s_vs  = scratch + OFF_VS;
    float* s_att = scratch + OFF_ATT;
    __half* hb = (__half*)(scratch + OFF_HALF);
    __half* acth = hb + H_ACTH;
    __half* wth  = hb + H_WTH;
    __half* wtl  = hb + H_WTL;
    __half* qwh  = hb + H_QWH;
    __half* kwh  = hb + H_KWH;
    __half* kwl  = hb + H_KWL;
    __half* vwh  = hb + H_VWH;
    __half* vwl  = hb + H_VWL;
    __half* csh  = hb + H_CSH;
    __half* cwh  = hb + H_CWH;
    __half* cath = hb + H_CATH;

    cudaFuncSetAttribute(gemm_cfg, cudaFuncAttributeMaxDynamicSharedMemorySize, HSMEM_BYTES);
    cudaFuncSetAttribute(word_attn_h6, cudaFuncAttributeMaxDynamicSharedMemorySize, WSMEM_BYTES);

    // prep
    ASplitArgs aa;
    aa.src[0] = q; aa.src[1] = k_s; aa.src[2] = v_s; aa.src[3] = k_w; aa.src[4] = v_w;
    act_split<<<dim3(256, 5), 256>>>(aa, acth);
    WSplitArgs wa;
    wa.src[0] = wq_s; wa.src[1] = wk_s; wa.src[2] = wv_s;
    wa.src[3] = wq_w; wa.src[4] = wk_w; wa.src[5] = wv_w;
    wa.src[6] = fcs_w; wa.src[7] = fcw_w; wa.src[8] = fco_w;
    w_transplit<<<dim3(16, 32, 9), dim3(32, 8)>>>(wa, wth, wtl);

    // all projections in ONE launch
    {
        GemmCfg c = {};
        c.K = 512; c.ldc = 512;
        c.Ah[0] = acth + AKW; c.Bh[0] = wth + WOFF(4); c.Bl[0] = wtl + WOFF(4);
        c.Ah[1] = acth + AVW; c.Bh[1] = wth + WOFF(5); c.Bl[1] = wtl + WOFF(5);
        c.Ah[2] = acth + AQ;  c.Bh[2] = wth + WOFF(0); c.Bl[2] = wtl + WOFF(0);
        c.Ah[3] = acth + AQ;  c.Bh[3] = wth + WOFF(3); c.Bl[3] = wtl + WOFF(3);
        c.Ah[4] = acth + AKS; c.Bh[4] = wth + WOFF(1); c.Bl[4] = wtl + WOFF(1);
        c.Ah[5] = acth + AVS; c.Bh[5] = wth + WOFF(2); c.Bl[5] = wtl + WOFF(2);
        c.bias[0] = bk_w; c.bias[1] = bv_w; c.bias[2] = bq_s;
        c.bias[3] = bq_w; c.bias[4] = bk_s; c.bias[5] = bv_s;
        c.bscale[0] = 1.f; c.bscale[1] = 1.f; c.bscale[2] = 1.f;
        c.bscale[3] = 0.125f; c.bscale[4] = 1.f; c.bscale[5] = 1.f;
        c.M[0] = 12288; c.M[1] = 12288; c.M[2] = 1024;
        c.M[3] = 1024;  c.M[4] = 96;    c.M[5] = 96;
        c.mode[0] = 1; c.mode[1] = 1; c.mode[2] = 0;
        c.mode[3] = 2; c.mode[4] = 0; c.mode[5] = 0;
        c.Ch[0] = kwh; c.Cl[0] = kwl;
        c.Ch[1] = vwh; c.Cl[1] = vwl;
        c.Cf[2] = s_qs;
        c.Ch[3] = qwh;
        c.Cf[4] = s_ks;
        c.Cf[5] = s_vs;
        gemm_cfg<<<dim3(8, 96, 6), 256, HSMEM_BYTES>>>(c);
    }

    sent_attn8<<<dim3(Hd, BB, 8), 256>>>(s_qs, s_ks, s_vs, bias_s, gab, s_att, csh);

    word_attn_h6<<<dim3(8, Hd, BB), 512, WSMEM_BYTES>>>(
        qwh, kwh, kwl, vwh, vwl, bias_w, s_att, cwh);

    // fcs / fcw -> fp16 cat (hi only; fco reads only cath)
    {
        GemmCfg c = {};
        c.K = 512; c.ldc = 1024;
        c.Ah[0] = csh; c.Bh[0] = wth + WOFF(6); c.Bl[0] = wtl + WOFF(6);
        c.Ah[1] = cwh; c.Bh[1] = wth + WOFF(7); c.Bl[1] = wtl + WOFF(7);
        c.bias[0] = fcs_b; c.bias[1] = fcw_b;
        c.bscale[0] = 1.f; c.bscale[1] = 1.f;
        c.M[0] = 1024; c.M[1] = 1024;
        c.mode[0] = 2; c.mode[1] = 2;
        c.Ch[0] = cath;
        c.Ch[1] = cath + 512;
        gemm_cfg<<<dim3(8, 8, 2), 256, HSMEM_BYTES>>>(c);
    }
    // final fco -> fp32 out
    {
        GemmCfg c = {};
        c.K = 1024; c.ldc = 512;
        c.Ah[0] = cath; c.Bh[0] = wth + WOFF(8); c.Bl[0] = wtl + WOFF(8);
        c.bias[0] = fco_b;
        c.bscale[0] = 1.f;
        c.M[0] = 1024;
        c.mode[0] = 0;
        c.Cf[0] = (float*)d_out;
        gemm_cfg<<<dim3(8, 8, 1), 256, HSMEM_BYTES>>>(c);
    }
}